// round 8
// baseline (speedup 1.0000x reference)
#include <cuda_runtime.h>
#include <cuda_fp16.h>
#include <math.h>
#include <stdint.h>

#define NN 100000
#define EE 1600000
#define ET (EE + NN)
#define F_IN 500
#define HID 16
#define HEADS 8
#define F1 (HEADS * HID)   // 128
#define NCLS 10

// ---------------- scratch (static device globals) ---------------------------
__device__ __half g_bufH[(size_t)NN * F1];   // fp16 features (gemm output)
__device__ float  g_bufA[(size_t)NN * F1];   // fp32 (layer-3 gemm out)
__device__ float  g_bufB[(size_t)NN * F1];   // fp32 aggregate output
__device__ float  g_als[(size_t)NN * HEADS];
__device__ float  g_ald[(size_t)NN * HEADS];
__device__ int    g_deg[NN];
__device__ int    g_rowptr[NN];
__device__ int    g_cursor[NN];
__device__ int    g_bsum[256];
__device__ int    g_boff[256];
__device__ int    g_csr[(size_t)ET];         // src node per CSR slot

static inline int cdiv(int a, int b) { return (a + b - 1) / b; }

__device__ __forceinline__ uint32_t smem_u32(const void* p) {
    uint32_t a;
    asm("{ .reg .u64 t; cvta.to.shared.u64 t, %1; cvt.u32.u64 %0, t; }"
        : "=r"(a) : "l"(p));
    return a;
}
__device__ __forceinline__ uint32_t rna(float v) {
    uint32_t t;
    asm("cvt.rna.tf32.f32 %0, %1;" : "=r"(t) : "f"(v));
    return t;
}

// ---------------- tiny utils -------------------------------------------------
__global__ void fill_i(int* p, int v, int n) {
    int i = blockIdx.x * blockDim.x + threadIdx.x;
    if (i < n) p[i] = v;
}

// ---------------- CSR build --------------------------------------------------
__global__ void hist_dst(const int* __restrict__ ei, int* __restrict__ deg) {
    int e = blockIdx.x * blockDim.x + threadIdx.x;
    if (e >= ET) return;
    int dst = (e < EE) ? ei[EE + e] : (e - EE);
    atomicAdd(&deg[dst], 1);
}

#define SCAN_ELEMS 512
__global__ void scan_s1(const int* __restrict__ deg, int* __restrict__ bsum) {
    __shared__ int sm[256];
    int base = blockIdx.x * SCAN_ELEMS;
    int t = threadIdx.x;
    int i0 = base + 2 * t, i1 = base + 2 * t + 1;
    int v = 0;
    if (i0 < NN) v += deg[i0];
    if (i1 < NN) v += deg[i1];
    sm[t] = v;
    __syncthreads();
    for (int off = 128; off > 0; off >>= 1) {
        if (t < off) sm[t] += sm[t + off];
        __syncthreads();
    }
    if (t == 0) bsum[blockIdx.x] = sm[0];
}
__global__ void scan_s2(const int* __restrict__ bsum, int* __restrict__ boff, int nb) {
    __shared__ int sm[256];
    int t = threadIdx.x;
    int v = (t < nb) ? bsum[t] : 0;
    sm[t] = v;
    __syncthreads();
    for (int off = 1; off < 256; off <<= 1) {
        int add = (t >= off) ? sm[t - off] : 0;
        __syncthreads();
        sm[t] += add;
        __syncthreads();
    }
    if (t < nb) boff[t] = sm[t] - v;   // exclusive
}
__global__ void scan_s3(const int* __restrict__ deg, const int* __restrict__ boff,
                        int* __restrict__ rowptr, int* __restrict__ cursor) {
    __shared__ int sm[256];
    int base = blockIdx.x * SCAN_ELEMS;
    int t = threadIdx.x;
    int i0 = base + 2 * t, i1 = base + 2 * t + 1;
    int v0 = (i0 < NN) ? deg[i0] : 0;
    int v1 = (i1 < NN) ? deg[i1] : 0;
    int s = v0 + v1;
    sm[t] = s;
    __syncthreads();
    for (int off = 1; off < 256; off <<= 1) {
        int add = (t >= off) ? sm[t - off] : 0;
        __syncthreads();
        sm[t] += add;
        __syncthreads();
    }
    int ex = sm[t] - s + boff[blockIdx.x];
    if (i0 < NN) { rowptr[i0] = ex;      cursor[i0] = ex; }
    if (i1 < NN) { rowptr[i1] = ex + v0; cursor[i1] = ex + v0; }
}

__global__ void csr_scatter(const int* __restrict__ ei, int* __restrict__ cursor,
                            int* __restrict__ csr) {
    int e = blockIdx.x * blockDim.x + threadIdx.x;
    if (e >= ET) return;
    int src, dst;
    if (e < EE) { src = ei[e]; dst = ei[EE + e]; }
    else        { src = dst = e - EE; }
    int pos = atomicAdd(&cursor[dst], 1);
    csr[pos] = src;
}

// ======== tf32 mma.sync GEMM, cp.async 3-stage, 512 threads ================
// C[M,128] = A[M,K] @ B[K,128]. Block 256x128, 16 warps (8x2), warp 32x64.
#define TM 256
#define KCH 16
#define ASTR 20
#define BSTR 136
#define ABYTES (TM * ASTR * 4)
#define BBYTES (KCH * BSTR * 4)
#define STAGEB (ABYTES + BBYTES)   // 29184
#define NSTAGE 3
#define GSMEM (NSTAGE * STAGEB)    // 87552

__global__ __launch_bounds__(512) void gemm_tc(const float* __restrict__ A,
                                               const float* __restrict__ B,
                                               __half* __restrict__ H,
                                               int M, int K) {
    extern __shared__ float smf[];
    uint32_t sbase = smem_u32(smf);
    int tid = threadIdx.x, lane = tid & 31, wid = tid >> 5;
    int wm = (wid & 7) * 32, wn = (wid >> 3) * 64;
    int row0 = blockIdx.x * TM;
    int gid = lane >> 2, tk = lane & 3;
    int niter = (K + KCH - 1) / KCH;

    float acc[2][8][4];
#pragma unroll
    for (int mi = 0; mi < 2; mi++)
#pragma unroll
        for (int ni = 0; ni < 8; ni++)
#pragma unroll
            for (int q = 0; q < 4; q++) acc[mi][ni][q] = 0.f;

    auto load_stage = [&](int s, int k0) {
        uint32_t aB = sbase + s * STAGEB;
        uint32_t bB = aB + ABYTES;
#pragma unroll
        for (int i = 0; i < 2; i++) {
            int id = tid + i * 512;          // 1024 chunks: A 256 rows x 4
            int r = id >> 2, c4 = id & 3;
            int gk = k0 + c4 * 4;
            const float* gp = A + (size_t)(row0 + r) * K + gk;
            int remain = K - gk;
            int bytes = 16;
            if (row0 + r >= M || remain <= 0) bytes = 0;
            else if (remain < 4) bytes = remain * 4;
            uint32_t dst = aB + (uint32_t)(r * ASTR + c4 * 4) * 4u;
            asm volatile("cp.async.ca.shared.global [%0], [%1], 16, %2;"
                         :: "r"(dst), "l"(gp), "r"(bytes));
        }
        {
            int id = tid;                    // 512 chunks: B 16 rows x 32
            int k = id >> 5, c4 = id & 31;
            const float* gp = B + (size_t)(k0 + k) * 128 + c4 * 4;
            int bytes = (k0 + k < K) ? 16 : 0;
            uint32_t dst = bB + (uint32_t)(k * BSTR + c4 * 4) * 4u;
            asm volatile("cp.async.ca.shared.global [%0], [%1], 16, %2;"
                         :: "r"(dst), "l"(gp), "r"(bytes));
        }
        asm volatile("cp.async.commit_group;");
    };

    load_stage(0, 0);
    if (niter > 1) load_stage(1, KCH);

    for (int it = 0; it < niter; it++) {
        if (it + 1 < niter) asm volatile("cp.async.wait_group 1;");
        else                asm volatile("cp.async.wait_group 0;");
        __syncthreads();
        if (it + 2 < niter) load_stage((it + 2) % NSTAGE, (it + 2) * KCH);

        const float* As = smf + ((it % NSTAGE) * STAGEB) / 4;
        const float* Bs = As + ABYTES / 4;
#pragma unroll
        for (int ks = 0; ks < 2; ks++) {
            int kb = ks * 8;
            uint32_t af[2][4];
#pragma unroll
            for (int mi = 0; mi < 2; mi++) {
                int r = wm + mi * 16 + gid;
                af[mi][0] = rna(As[r * ASTR + kb + tk]);
                af[mi][1] = rna(As[(r + 8) * ASTR + kb + tk]);
                af[mi][2] = rna(As[r * ASTR + kb + tk + 4]);
                af[mi][3] = rna(As[(r + 8) * ASTR + kb + tk + 4]);
            }
            uint32_t bf[8][2];
#pragma unroll
            for (int ni = 0; ni < 8; ni++) {
                int c = wn + ni * 8 + gid;
                bf[ni][0] = rna(Bs[(kb + tk) * BSTR + c]);
                bf[ni][1] = rna(Bs[(kb + tk + 4) * BSTR + c]);
            }
#pragma unroll
            for (int mi = 0; mi < 2; mi++)
#pragma unroll
                for (int ni = 0; ni < 8; ni++) {
                    asm volatile(
                        "mma.sync.aligned.m16n8k8.row.col.f32.tf32.tf32.f32 "
                        "{%0,%1,%2,%3}, {%4,%5,%6,%7}, {%8,%9}, {%0,%1,%2,%3};"
                        : "+f"(acc[mi][ni][0]), "+f"(acc[mi][ni][1]),
                          "+f"(acc[mi][ni][2]), "+f"(acc[mi][ni][3])
                        : "r"(af[mi][0]), "r"(af[mi][1]), "r"(af[mi][2]), "r"(af[mi][3]),
                          "r"(bf[ni][0]), "r"(bf[ni][1]));
                }
        }
        __syncthreads();
    }

#pragma unroll
    for (int mi = 0; mi < 2; mi++) {
        int r0 = row0 + wm + mi * 16 + gid;
        int r1 = r0 + 8;
#pragma unroll
        for (int ni = 0; ni < 8; ni++) {
            int c = wn + ni * 8 + tk * 2;
            if (r0 < M)
                *(__half2*)(H + (size_t)r0 * 128 + c) =
                    __floats2half2_rn(acc[mi][ni][0], acc[mi][ni][1]);
            if (r1 < M)
                *(__half2*)(H + (size_t)r1 * 128 + c) =
                    __floats2half2_rn(acc[mi][ni][2], acc[mi][ni][3]);
        }
    }
}

// ---------------- node alphas from fp16 features, warp per node --------------
__global__ __launch_bounds__(256) void node_alpha_w(const __half* __restrict__ h,
                                                    const float* __restrict__ a_src,
                                                    const float* __restrict__ a_dst,
                                                    float* __restrict__ als,
                                                    float* __restrict__ ald) {
    __shared__ float s_as[F1], s_ad[F1];
    int t = threadIdx.x;
    if (t < F1) { s_as[t] = a_src[t]; s_ad[t] = a_dst[t]; }
    __syncthreads();
    int warp = (blockIdx.x * blockDim.x + t) >> 5;
    int lane = t & 31;
    if (warp >= NN) return;
    int c0 = lane * 4;
    const __half2* hp = (const __half2*)(h + (size_t)warp * F1) + lane * 2;
    float2 v0 = __half22float2(hp[0]);
    float2 v1 = __half22float2(hp[1]);
    float s = v0.x * s_as[c0] + v0.y * s_as[c0 + 1] + v1.x * s_as[c0 + 2] + v1.y * s_as[c0 + 3];
    float d = v0.x * s_ad[c0] + v0.y * s_ad[c0 + 1] + v1.x * s_ad[c0 + 2] + v1.y * s_ad[c0 + 3];
    s += __shfl_xor_sync(0xffffffffu, s, 1);
    s += __shfl_xor_sync(0xffffffffu, s, 2);
    d += __shfl_xor_sync(0xffffffffu, d, 1);
    d += __shfl_xor_sync(0xffffffffu, d, 2);
    if ((lane & 3) == 0) {
        int hh = lane >> 2;
        als[(size_t)warp * HEADS + hh] = s;
        ald[(size_t)warp * HEADS + hh] = d;
    }
}

// ---------------- fused aggregation (layers 1,2) -----------------------------
__global__ __launch_bounds__(128) void aggregate_fused(
    const int* __restrict__ csr, const int* __restrict__ rowptr,
    const int* __restrict__ deg, const float* __restrict__ als,
    const float* __restrict__ ald, const __half* __restrict__ hfeat,
    const float* __restrict__ bias, const float* __restrict__ gamma,
    const float* __restrict__ beta, float* __restrict__ out) {
    __shared__ float4 s_acc[3][32];
    __shared__ float  s_d[4][8];
    int n = blockIdx.x;
    int t = threadIdx.x;
    int w = t >> 5, l = t & 31;
    int h = l >> 2;
    int c0 = l * 4;
    int start = rowptr[n];
    int len = deg[n];
    float myald = __ldg(&ald[(size_t)n * HEADS + h]);

    float4 acc = make_float4(0.f, 0.f, 0.f, 0.f);
    float dsum = 0.f;

    auto edge = [&](int s) {
        const __half2* hp = (const __half2*)(hfeat + (size_t)s * F1) + l * 2;
        __half2 q0 = __ldg(hp);
        __half2 q1 = __ldg(hp + 1);
        float al = __ldg(&als[(size_t)s * HEADS + h]) + myald;
        al = al > 0.f ? al : 0.2f * al;
        float p = __expf(al);
        dsum += p;
        float2 f0 = __half22float2(q0);
        float2 f1 = __half22float2(q1);
        acc.x = fmaf(p, f0.x, acc.x);
        acc.y = fmaf(p, f0.y, acc.y);
        acc.z = fmaf(p, f1.x, acc.z);
        acc.w = fmaf(p, f1.y, acc.w);
    };

    int i = w;
    for (; i + 4 < len; i += 8) {
        int s0 = __ldg(&csr[start + i]);
        int s1 = __ldg(&csr[start + i + 4]);
        edge(s0);
        edge(s1);
    }
    if (i < len) {
        int s0 = __ldg(&csr[start + i]);
        edge(s0);
    }

    if (w > 0) s_acc[w - 1][l] = acc;
    if ((l & 3) == 0) s_d[w][h] = dsum;
    __syncthreads();
    if (w == 0) {
        float4 a1 = s_acc[0][l], a2 = s_acc[1][l], a3 = s_acc[2][l];
        acc.x += a1.x + a2.x + a3.x;
        acc.y += a1.y + a2.y + a3.y;
        acc.z += a1.z + a2.z + a3.z;
        acc.w += a1.w + a2.w + a3.w;
        float dall = s_d[0][h] + s_d[1][h] + s_d[2][h] + s_d[3][h];
        float invd = 1.f / fmaxf(dall, 1e-16f);
        float4 bb = *(const float4*)(bias + c0);
        float4 gg = *(const float4*)(gamma + c0);
        float4 be = *(const float4*)(beta + c0);
        float bnf = rsqrtf(1.0f + 1e-5f);
        float v0 = acc.x * invd + bb.x;
        float v1 = acc.y * invd + bb.y;
        float v2 = acc.z * invd + bb.z;
        float v3 = acc.w * invd + bb.w;
        v0 = v0 > 0.f ? v0 : (__expf(v0) - 1.f);
        v1 = v1 > 0.f ? v1 : (__expf(v1) - 1.f);
        v2 = v2 > 0.f ? v2 : (__expf(v2) - 1.f);
        v3 = v3 > 0.f ? v3 : (__expf(v3) - 1.f);
        float4 r;
        r.x = v0 * gg.x * bnf + be.x;
        r.y = v1 * gg.y * bnf + be.y;
        r.z = v2 * gg.z * bnf + be.z;
        r.w = v3 * gg.w * bnf + be.w;
        *(float4*)(out + (size_t)n * F1 + c0) = r;
    }
}

// ---------------- layer 3: fused GEMM(128->10) + node alphas ----------------
__global__ void gemm10_alpha(const float* __restrict__ A, const float* __restrict__ W,
                             const float* __restrict__ a3s, const float* __restrict__ a3d,
                             float* __restrict__ C, float* __restrict__ als,
                             float* __restrict__ ald) {
    __shared__ float Ws[F1 * NCLS];
    for (int i = threadIdx.x; i < F1 * NCLS; i += blockDim.x) Ws[i] = W[i];
    __syncthreads();
    int warp = (blockIdx.x * blockDim.x + threadIdx.x) >> 5;
    int lane = threadIdx.x & 31;
    if (warp >= NN) return;
    float acc[NCLS];
#pragma unroll
    for (int c = 0; c < NCLS; c++) acc[c] = 0.f;
    const float* arow = A + (size_t)warp * F1;
#pragma unroll
    for (int q = 0; q < 4; q++) {
        int k = lane + q * 32;
        float a = arow[k];
#pragma unroll
        for (int c = 0; c < NCLS; c++) acc[c] += a * Ws[k * NCLS + c];
    }
#pragma unroll
    for (int off = 16; off > 0; off >>= 1)
#pragma unroll
        for (int c = 0; c < NCLS; c++) acc[c] += __shfl_xor_sync(0xffffffffu, acc[c], off);
    if (lane < NCLS) C[(size_t)warp * NCLS + lane] = acc[lane];
    if (lane == 0) {
        float s = 0.f, d = 0.f;
#pragma unroll
        for (int c = 0; c < NCLS; c++) {
            s += acc[c] * __ldg(&a3s[c]);
            d += acc[c] * __ldg(&a3d[c]);
        }
        als[warp] = s;
        ald[warp] = d;
    }
}

// ---------------- layer 3: fused aggregation + bias + log_softmax ------------
__global__ __launch_bounds__(128) void aggregate10_lsm(
    const int* __restrict__ csr, const int* __restrict__ rowptr,
    const int* __restrict__ deg, const float* __restrict__ als,
    const float* __restrict__ ald, const float* __restrict__ hfeat,
    const float* __restrict__ b3, float* __restrict__ out) {
    int warp = (blockIdx.x * blockDim.x + threadIdx.x) >> 5;
    int lane = threadIdx.x & 31;
    if (warp >= NN) return;
    int n = warp;
    int start = rowptr[n];
    int len = deg[n];
    float myald = (lane == 0) ? __ldg(&ald[n]) : 0.f;
    float acc = 0.f, dsum = 0.f;
    int i = 0;
    for (; i + 2 <= len; i += 2) {
        int s0 = __ldg(&csr[start + i]);
        int s1 = __ldg(&csr[start + i + 1]);
        float f0 = (lane < NCLS) ? __ldg(&hfeat[(size_t)s0 * NCLS + lane]) : 0.f;
        float f1 = (lane < NCLS) ? __ldg(&hfeat[(size_t)s1 * NCLS + lane]) : 0.f;
        float p0 = 0.f, p1 = 0.f;
        if (lane == 0) {
            float l0 = __ldg(&als[s0]) + myald;
            float l1 = __ldg(&als[s1]) + myald;
            l0 = l0 > 0.f ? l0 : 0.2f * l0;
            l1 = l1 > 0.f ? l1 : 0.2f * l1;
            p0 = __expf(l0);
            p1 = __expf(l1);
        }
        p0 = __shfl_sync(0xffffffffu, p0, 0);
        p1 = __shfl_sync(0xffffffffu, p1, 0);
        dsum += p0 + p1;
        acc = fmaf(p0, f0, fmaf(p1, f1, acc));
    }
    if (i < len) {
        int s0 = __ldg(&csr[start + i]);
        float f0 = (lane < NCLS) ? __ldg(&hfeat[(size_t)s0 * NCLS + lane]) : 0.f;
        float p0 = 0.f;
        if (lane == 0) {
            float l0 = __ldg(&als[s0]) + myald;
            l0 = l0 > 0.f ? l0 : 0.2f * l0;
            p0 = __expf(l0);
        }
        p0 = __shfl_sync(0xffffffffu, p0, 0);
        dsum += p0;
        acc = fmaf(p0, f0, acc);
    }
    float invd = 1.f / fmaxf(dsum, 1e-16f);
    float val = (lane < NCLS) ? acc * invd + __ldg(&b3[lane]) : -1e30f;
    float m = val;
#pragma unroll
    for (int off = 16; off > 0; off >>= 1)
        m = fmaxf(m, __shfl_xor_sync(0xffffffffu, m, off));
    float ex = (lane < NCLS) ? expf(val - m) : 0.f;
    float ssum = ex;
#pragma unroll
    for (int off = 16; off > 0; off >>= 1)
        ssum += __shfl_xor_sync(0xffffffffu, ssum, off);
    float l = m + logf(ssum);
    if (lane < NCLS) out[(size_t)n * NCLS + lane] = val - l;
}

// ---------------- driver -----------------------------------------------------
extern "C" void kernel_launch(void* const* d_in, const int* in_sizes, int n_in,
                              void* d_out, int out_size) {
    const float* x    = (const float*)d_in[0];
    const int*   ei   = (const int*)d_in[1];
    const float* W1   = (const float*)d_in[2];
    const float* a1s  = (const float*)d_in[3];
    const float* a1d  = (const float*)d_in[4];
    const float* b1   = (const float*)d_in[5];
    const float* g1   = (const float*)d_in[6];
    const float* be1  = (const float*)d_in[7];
    const float* W2   = (const float*)d_in[8];
    const float* a2s  = (const float*)d_in[9];
    const float* a2d  = (const float*)d_in[10];
    const float* b2   = (const float*)d_in[11];
    const float* g2   = (const float*)d_in[12];
    const float* be2  = (const float*)d_in[13];
    const float* W3   = (const float*)d_in[14];
    const float* a3s  = (const float*)d_in[15];
    const float* a3d  = (const float*)d_in[16];
    const float* b3   = (const float*)d_in[17];
    float* out = (float*)d_out;

    __half* bufH;
    float *bufA, *bufB, *als, *ald;
    int *deg, *rowptr, *cursor, *bsum, *boff, *csr;
    cudaGetSymbolAddress((void**)&bufH, g_bufH);
    cudaGetSymbolAddress((void**)&bufA, g_bufA);
    cudaGetSymbolAddress((void**)&bufB, g_bufB);
    cudaGetSymbolAddress((void**)&als, g_als);
    cudaGetSymbolAddress((void**)&ald, g_ald);
    cudaGetSymbolAddress((void**)&deg, g_deg);
    cudaGetSymbolAddress((void**)&rowptr, g_rowptr);
    cudaGetSymbolAddress((void**)&cursor, g_cursor);
    cudaGetSymbolAddress((void**)&bsum, g_bsum);
    cudaGetSymbolAddress((void**)&boff, g_boff);
    cudaGetSymbolAddress((void**)&csr, g_csr);

    cudaFuncSetAttribute(gemm_tc, cudaFuncAttributeMaxDynamicSharedMemorySize, GSMEM);

    const int TB = 256;
    const int NB_SCAN = cdiv(NN, SCAN_ELEMS);
    const int NGRID = cdiv(NN, TM);

    // launches 0-2: CSR prep; launch 3 = gemm_tc (ncu capture idx 3)
    fill_i<<<cdiv(NN, TB), TB>>>(deg, 0, NN);
    hist_dst<<<cdiv(ET, TB), TB>>>(ei, deg);
    scan_s1<<<NB_SCAN, 256>>>(deg, bsum);

    gemm_tc<<<NGRID, 512, GSMEM>>>(x, W1, bufH, NN, F_IN);          // layer 1 GEMM

    scan_s2<<<1, 256>>>(bsum, boff, NB_SCAN);
    scan_s3<<<NB_SCAN, 256>>>(deg, boff, rowptr, cursor);
    csr_scatter<<<cdiv(ET, TB), TB>>>(ei, cursor, csr);

    // ---- layer 1 rest ----
    node_alpha_w<<<cdiv(NN * 32, TB), TB>>>(bufH, a1s, a1d, als, ald);
    aggregate_fused<<<NN, 128>>>(csr, rowptr, deg, als, ald, bufH, b1, g1, be1, bufB);

    // ---- layer 2 ----
    gemm_tc<<<NGRID, 512, GSMEM>>>(bufB, W2, bufH, NN, F1);
    node_alpha_w<<<cdiv(NN * 32, TB), TB>>>(bufH, a2s, a2d, als, ald);
    aggregate_fused<<<NN, 128>>>(csr, rowptr, deg, als, ald, bufH, b2, g2, be2, bufB);

    // ---- layer 3 ----
    gemm10_alpha<<<cdiv(NN * 32, TB), TB>>>(bufB, W3, a3s, a3d, bufA, als, ald);
    aggregate10_lsm<<<cdiv(NN * 32, 128), 128>>>(csr, rowptr, deg, als, ald, bufA, b3, out);
}

// round 9
// speedup vs baseline: 1.0598x; 1.0598x over previous
#include <cuda_runtime.h>
#include <cuda_fp16.h>
#include <math.h>
#include <stdint.h>

#define NN 100000
#define EE 1600000
#define ET (EE + NN)
#define F_IN 500
#define HID 16
#define HEADS 8
#define F1 (HEADS * HID)   // 128
#define NCLS 10

// ---------------- scratch (static device globals) ---------------------------
__device__ __half g_bufH[(size_t)NN * F1];   // fp16 features (gemm output)
__device__ float  g_bufA[(size_t)NN * F1];   // fp32 (layer-3 gemm out)
__device__ float  g_bufB[(size_t)NN * F1];   // fp32 aggregate output
__device__ float  g_als[(size_t)NN * HEADS];
__device__ float  g_ald[(size_t)NN * HEADS];
__device__ int    g_deg[NN];
__device__ int    g_rowptr[NN];
__device__ int    g_cursor[NN];
__device__ int    g_bsum[256];
__device__ int    g_boff[256];
__device__ int    g_csr[(size_t)ET];         // src node per CSR slot

static inline int cdiv(int a, int b) { return (a + b - 1) / b; }

__device__ __forceinline__ uint32_t smem_u32(const void* p) {
    uint32_t a;
    asm("{ .reg .u64 t; cvta.to.shared.u64 t, %1; cvt.u32.u64 %0, t; }"
        : "=r"(a) : "l"(p));
    return a;
}

// ---------------- tiny utils -------------------------------------------------
__global__ void fill_i(int* p, int v, int n) {
    int i = blockIdx.x * blockDim.x + threadIdx.x;
    if (i < n) p[i] = v;
}

// ---------------- CSR build --------------------------------------------------
__global__ void hist_dst(const int* __restrict__ ei, int* __restrict__ deg) {
    int e = blockIdx.x * blockDim.x + threadIdx.x;
    if (e >= ET) return;
    int dst = (e < EE) ? ei[EE + e] : (e - EE);
    atomicAdd(&deg[dst], 1);
}

#define SCAN_ELEMS 512
__global__ void scan_s1(const int* __restrict__ deg, int* __restrict__ bsum) {
    __shared__ int sm[256];
    int base = blockIdx.x * SCAN_ELEMS;
    int t = threadIdx.x;
    int i0 = base + 2 * t, i1 = base + 2 * t + 1;
    int v = 0;
    if (i0 < NN) v += deg[i0];
    if (i1 < NN) v += deg[i1];
    sm[t] = v;
    __syncthreads();
    for (int off = 128; off > 0; off >>= 1) {
        if (t < off) sm[t] += sm[t + off];
        __syncthreads();
    }
    if (t == 0) bsum[blockIdx.x] = sm[0];
}
__global__ void scan_s2(const int* __restrict__ bsum, int* __restrict__ boff, int nb) {
    __shared__ int sm[256];
    int t = threadIdx.x;
    int v = (t < nb) ? bsum[t] : 0;
    sm[t] = v;
    __syncthreads();
    for (int off = 1; off < 256; off <<= 1) {
        int add = (t >= off) ? sm[t - off] : 0;
        __syncthreads();
        sm[t] += add;
        __syncthreads();
    }
    if (t < nb) boff[t] = sm[t] - v;   // exclusive
}
__global__ void scan_s3(const int* __restrict__ deg, const int* __restrict__ boff,
                        int* __restrict__ rowptr, int* __restrict__ cursor) {
    __shared__ int sm[256];
    int base = blockIdx.x * SCAN_ELEMS;
    int t = threadIdx.x;
    int i0 = base + 2 * t, i1 = base + 2 * t + 1;
    int v0 = (i0 < NN) ? deg[i0] : 0;
    int v1 = (i1 < NN) ? deg[i1] : 0;
    int s = v0 + v1;
    sm[t] = s;
    __syncthreads();
    for (int off = 1; off < 256; off <<= 1) {
        int add = (t >= off) ? sm[t - off] : 0;
        __syncthreads();
        sm[t] += add;
        __syncthreads();
    }
    int ex = sm[t] - s + boff[blockIdx.x];
    if (i0 < NN) { rowptr[i0] = ex;      cursor[i0] = ex; }
    if (i1 < NN) { rowptr[i1] = ex + v0; cursor[i1] = ex + v0; }
}

__global__ void csr_scatter(const int* __restrict__ ei, int* __restrict__ cursor,
                            int* __restrict__ csr) {
    int e = blockIdx.x * blockDim.x + threadIdx.x;
    if (e >= ET) return;
    int src, dst;
    if (e < EE) { src = ei[e]; dst = ei[EE + e]; }
    else        { src = dst = e - EE; }
    int pos = atomicAdd(&cursor[dst], 1);
    csr[pos] = src;
}

// ======== tf32 mma.sync GEMM + fused alpha epilogue =========================
// C[M,128] = A[M,K] @ B[K,128]. Block 256x128, 8 warps (4x2), warp 64x64.
// Raw fp32 bits fed to tf32 MMA (truncation). Epilogue computes per-head
// src/dst attention dots and writes fp16 features.
#define TM 256
#define KCH 16
#define ASTR 20
#define BSTR 136
#define ABYTES (TM * ASTR * 4)
#define BBYTES (KCH * BSTR * 4)
#define STAGEB (ABYTES + BBYTES)
#define GSMEM (2 * STAGEB)

__global__ __launch_bounds__(256) void gemm_tc(const float* __restrict__ A,
                                               const float* __restrict__ B,
                                               __half* __restrict__ H,
                                               const float* __restrict__ a_src,
                                               const float* __restrict__ a_dst,
                                               float* __restrict__ als,
                                               float* __restrict__ ald,
                                               int M, int K) {
    extern __shared__ float smf[];
    __shared__ float s_as[F1], s_ad[F1];
    uint32_t sbase = smem_u32(smf);
    int tid = threadIdx.x, lane = tid & 31, wid = tid >> 5;
    int wm = (wid & 3) * 64, wn = (wid >> 2) * 64;
    int row0 = blockIdx.x * TM;
    int gid = lane >> 2, tk = lane & 3;
    int niter = (K + KCH - 1) / KCH;

    if (tid < F1) s_as[tid] = a_src[tid];
    else if (tid < 2 * F1) s_ad[tid - F1] = a_dst[tid - F1];

    float acc[4][8][4];
#pragma unroll
    for (int mi = 0; mi < 4; mi++)
#pragma unroll
        for (int ni = 0; ni < 8; ni++)
#pragma unroll
            for (int q = 0; q < 4; q++) acc[mi][ni][q] = 0.f;

    auto load_stage = [&](int s, int k0) {
        uint32_t aB = sbase + s * STAGEB;
        uint32_t bB = aB + ABYTES;
#pragma unroll
        for (int i = 0; i < 4; i++) {
            int id = tid + i * 256;
            int r = id >> 2, c4 = id & 3;
            int gk = k0 + c4 * 4;
            const float* gp = A + (size_t)(row0 + r) * K + gk;
            int remain = K - gk;
            int bytes = 16;
            if (row0 + r >= M || remain <= 0) bytes = 0;
            else if (remain < 4) bytes = remain * 4;
            uint32_t dst = aB + (uint32_t)(r * ASTR + c4 * 4) * 4u;
            asm volatile("cp.async.ca.shared.global [%0], [%1], 16, %2;"
                         :: "r"(dst), "l"(gp), "r"(bytes));
        }
#pragma unroll
        for (int i = 0; i < 2; i++) {
            int id = tid + i * 256;
            int k = id >> 5, c4 = id & 31;
            const float* gp = B + (size_t)(k0 + k) * 128 + c4 * 4;
            int bytes = (k0 + k < K) ? 16 : 0;
            uint32_t dst = bB + (uint32_t)(k * BSTR + c4 * 4) * 4u;
            asm volatile("cp.async.ca.shared.global [%0], [%1], 16, %2;"
                         :: "r"(dst), "l"(gp), "r"(bytes));
        }
        asm volatile("cp.async.commit_group;");
    };

    load_stage(0, 0);

    for (int it = 0; it < niter; it++) {
        if (it + 1 < niter) {
            load_stage((it + 1) & 1, (it + 1) * KCH);
            asm volatile("cp.async.wait_group 1;");
        } else {
            asm volatile("cp.async.wait_group 0;");
        }
        __syncthreads();
        const float* As = smf + ((it & 1) * STAGEB) / 4;
        const float* Bs = As + ABYTES / 4;
#pragma unroll
        for (int ks = 0; ks < 2; ks++) {
            int kb = ks * 8;
            uint32_t af[4][4];
#pragma unroll
            for (int mi = 0; mi < 4; mi++) {
                int r = wm + mi * 16 + gid;
                af[mi][0] = __float_as_uint(As[r * ASTR + kb + tk]);
                af[mi][1] = __float_as_uint(As[(r + 8) * ASTR + kb + tk]);
                af[mi][2] = __float_as_uint(As[r * ASTR + kb + tk + 4]);
                af[mi][3] = __float_as_uint(As[(r + 8) * ASTR + kb + tk + 4]);
            }
            uint32_t bf[8][2];
#pragma unroll
            for (int ni = 0; ni < 8; ni++) {
                int c = wn + ni * 8 + gid;
                bf[ni][0] = __float_as_uint(Bs[(kb + tk) * BSTR + c]);
                bf[ni][1] = __float_as_uint(Bs[(kb + tk + 4) * BSTR + c]);
            }
#pragma unroll
            for (int mi = 0; mi < 4; mi++)
#pragma unroll
                for (int ni = 0; ni < 8; ni++) {
                    asm volatile(
                        "mma.sync.aligned.m16n8k8.row.col.f32.tf32.tf32.f32 "
                        "{%0,%1,%2,%3}, {%4,%5,%6,%7}, {%8,%9}, {%0,%1,%2,%3};"
                        : "+f"(acc[mi][ni][0]), "+f"(acc[mi][ni][1]),
                          "+f"(acc[mi][ni][2]), "+f"(acc[mi][ni][3])
                        : "r"(af[mi][0]), "r"(af[mi][1]), "r"(af[mi][2]), "r"(af[mi][3]),
                          "r"(bf[ni][0]), "r"(bf[ni][1]));
                }
        }
        __syncthreads();
    }

    // ---- fused alpha epilogue: heads wn/16 .. wn/16+3 handled by this warp ----
#pragma unroll
    for (int mi = 0; mi < 4; mi++) {
#pragma unroll
        for (int half = 0; half < 2; half++) {
            int row = row0 + wm + mi * 16 + half * 8 + gid;
#pragma unroll
            for (int hl = 0; hl < 4; hl++) {
                float ps = 0.f, pd = 0.f;
#pragma unroll
                for (int nj = 0; nj < 2; nj++) {
                    int ni = hl * 2 + nj;
                    int c0 = wn + ni * 8 + tk * 2;
                    float q0 = acc[mi][ni][half * 2 + 0];
                    float q1 = acc[mi][ni][half * 2 + 1];
                    ps += q0 * s_as[c0] + q1 * s_as[c0 + 1];
                    pd += q0 * s_ad[c0] + q1 * s_ad[c0 + 1];
                }
                ps += __shfl_xor_sync(0xffffffffu, ps, 1);
                ps += __shfl_xor_sync(0xffffffffu, ps, 2);
                pd += __shfl_xor_sync(0xffffffffu, pd, 1);
                pd += __shfl_xor_sync(0xffffffffu, pd, 2);
                if (tk == 0 && row < M) {
                    int h = (wn >> 4) + hl;
                    als[(size_t)row * HEADS + h] = ps;
                    ald[(size_t)row * HEADS + h] = pd;
                }
            }
        }
    }

    // ---- fp16 feature store ----
#pragma unroll
    for (int mi = 0; mi < 4; mi++) {
        int r0 = row0 + wm + mi * 16 + gid;
        int r1 = r0 + 8;
#pragma unroll
        for (int ni = 0; ni < 8; ni++) {
            int c = wn + ni * 8 + tk * 2;
            if (r0 < M)
                *(__half2*)(H + (size_t)r0 * 128 + c) =
                    __floats2half2_rn(acc[mi][ni][0], acc[mi][ni][1]);
            if (r1 < M)
                *(__half2*)(H + (size_t)r1 * 128 + c) =
                    __floats2half2_rn(acc[mi][ni][2], acc[mi][ni][3]);
        }
    }
}

// ---------------- fused aggregation (layers 1,2) -----------------------------
__global__ __launch_bounds__(128) void aggregate_fused(
    const int* __restrict__ csr, const int* __restrict__ rowptr,
    const int* __restrict__ deg, const float* __restrict__ als,
    const float* __restrict__ ald, const __half* __restrict__ hfeat,
    const float* __restrict__ bias, const float* __restrict__ gamma,
    const float* __restrict__ beta, float* __restrict__ out) {
    __shared__ float4 s_acc[3][32];
    __shared__ float  s_d[4][8];
    int n = blockIdx.x;
    int t = threadIdx.x;
    int w = t >> 5, l = t & 31;
    int h = l >> 2;
    int c0 = l * 4;
    int start = rowptr[n];
    int len = deg[n];
    float myald = __ldg(&ald[(size_t)n * HEADS + h]);

    float4 acc = make_float4(0.f, 0.f, 0.f, 0.f);
    float dsum = 0.f;

    auto edge = [&](int s) {
        const __half2* hp = (const __half2*)(hfeat + (size_t)s * F1) + l * 2;
        __half2 q0 = __ldg(hp);
        __half2 q1 = __ldg(hp + 1);
        float al = __ldg(&als[(size_t)s * HEADS + h]) + myald;
        al = al > 0.f ? al : 0.2f * al;
        float p = __expf(al);
        dsum += p;
        float2 f0 = __half22float2(q0);
        float2 f1 = __half22float2(q1);
        acc.x = fmaf(p, f0.x, acc.x);
        acc.y = fmaf(p, f0.y, acc.y);
        acc.z = fmaf(p, f1.x, acc.z);
        acc.w = fmaf(p, f1.y, acc.w);
    };

    int i = w;
    for (; i + 4 < len; i += 8) {
        int s0 = __ldg(&csr[start + i]);
        int s1 = __ldg(&csr[start + i + 4]);
        edge(s0);
        edge(s1);
    }
    if (i < len) {
        int s0 = __ldg(&csr[start + i]);
        edge(s0);
    }

    if (w > 0) s_acc[w - 1][l] = acc;
    if ((l & 3) == 0) s_d[w][h] = dsum;
    __syncthreads();
    if (w == 0) {
        float4 a1 = s_acc[0][l], a2 = s_acc[1][l], a3 = s_acc[2][l];
        acc.x += a1.x + a2.x + a3.x;
        acc.y += a1.y + a2.y + a3.y;
        acc.z += a1.z + a2.z + a3.z;
        acc.w += a1.w + a2.w + a3.w;
        float dall = s_d[0][h] + s_d[1][h] + s_d[2][h] + s_d[3][h];
        float invd = 1.f / fmaxf(dall, 1e-16f);
        float4 bb = *(const float4*)(bias + c0);
        float4 gg = *(const float4*)(gamma + c0);
        float4 be = *(const float4*)(beta + c0);
        float bnf = rsqrtf(1.0f + 1e-5f);
        float v0 = acc.x * invd + bb.x;
        float v1 = acc.y * invd + bb.y;
        float v2 = acc.z * invd + bb.z;
        float v3 = acc.w * invd + bb.w;
        v0 = v0 > 0.f ? v0 : (__expf(v0) - 1.f);
        v1 = v1 > 0.f ? v1 : (__expf(v1) - 1.f);
        v2 = v2 > 0.f ? v2 : (__expf(v2) - 1.f);
        v3 = v3 > 0.f ? v3 : (__expf(v3) - 1.f);
        float4 r;
        r.x = v0 * gg.x * bnf + be.x;
        r.y = v1 * gg.y * bnf + be.y;
        r.z = v2 * gg.z * bnf + be.z;
        r.w = v3 * gg.w * bnf + be.w;
        *(float4*)(out + (size_t)n * F1 + c0) = r;
    }
}

// ---------------- layer 3: fused GEMM(128->10) + node alphas ----------------
__global__ void gemm10_alpha(const float* __restrict__ A, const float* __restrict__ W,
                             const float* __restrict__ a3s, const float* __restrict__ a3d,
                             float* __restrict__ C, float* __restrict__ als,
                             float* __restrict__ ald) {
    __shared__ float Ws[F1 * NCLS];
    for (int i = threadIdx.x; i < F1 * NCLS; i += blockDim.x) Ws[i] = W[i];
    __syncthreads();
    int warp = (blockIdx.x * blockDim.x + threadIdx.x) >> 5;
    int lane = threadIdx.x & 31;
    if (warp >= NN) return;
    float acc[NCLS];
#pragma unroll
    for (int c = 0; c < NCLS; c++) acc[c] = 0.f;
    const float* arow = A + (size_t)warp * F1;
#pragma unroll
    for (int q = 0; q < 4; q++) {
        int k = lane + q * 32;
        float a = arow[k];
#pragma unroll
        for (int c = 0; c < NCLS; c++) acc[c] += a * Ws[k * NCLS + c];
    }
#pragma unroll
    for (int off = 16; off > 0; off >>= 1)
#pragma unroll
        for (int c = 0; c < NCLS; c++) acc[c] += __shfl_xor_sync(0xffffffffu, acc[c], off);
    if (lane < NCLS) C[(size_t)warp * NCLS + lane] = acc[lane];
    if (lane == 0) {
        float s = 0.f, d = 0.f;
#pragma unroll
        for (int c = 0; c < NCLS; c++) {
            s += acc[c] * __ldg(&a3s[c]);
            d += acc[c] * __ldg(&a3d[c]);
        }
        als[warp] = s;
        ald[warp] = d;
    }
}

// ---------------- layer 3: fused aggregation + bias + log_softmax ------------
__global__ __launch_bounds__(128) void aggregate10_lsm(
    const int* __restrict__ csr, const int* __restrict__ rowptr,
    const int* __restrict__ deg, const float* __restrict__ als,
    const float* __restrict__ ald, const float* __restrict__ hfeat,
    const float* __restrict__ b3, float* __restrict__ out) {
    int warp = (blockIdx.x * blockDim.x + threadIdx.x) >> 5;
    int lane = threadIdx.x & 31;
    if (warp >= NN) return;
    int n = warp;
    int start = rowptr[n];
    int len = deg[n];
    float myald = (lane == 0) ? __ldg(&ald[n]) : 0.f;
    float acc = 0.f, dsum = 0.f;
    int i = 0;
    for (; i + 2 <= len; i += 2) {
        int s0 = __ldg(&csr[start + i]);
        int s1 = __ldg(&csr[start + i + 1]);
        float f0 = (lane < NCLS) ? __ldg(&hfeat[(size_t)s0 * NCLS + lane]) : 0.f;
        float f1 = (lane < NCLS) ? __ldg(&hfeat[(size_t)s1 * NCLS + lane]) : 0.f;
        float p0 = 0.f, p1 = 0.f;
        if (lane == 0) {
            float l0 = __ldg(&als[s0]) + myald;
            float l1 = __ldg(&als[s1]) + myald;
            l0 = l0 > 0.f ? l0 : 0.2f * l0;
            l1 = l1 > 0.f ? l1 : 0.2f * l1;
            p0 = __expf(l0);
            p1 = __expf(l1);
        }
        p0 = __shfl_sync(0xffffffffu, p0, 0);
        p1 = __shfl_sync(0xffffffffu, p1, 0);
        dsum += p0 + p1;
        acc = fmaf(p0, f0, fmaf(p1, f1, acc));
    }
    if (i < len) {
        int s0 = __ldg(&csr[start + i]);
        float f0 = (lane < NCLS) ? __ldg(&hfeat[(size_t)s0 * NCLS + lane]) : 0.f;
        float p0 = 0.f;
        if (lane == 0) {
            float l0 = __ldg(&als[s0]) + myald;
            l0 = l0 > 0.f ? l0 : 0.2f * l0;
            p0 = __expf(l0);
        }
        p0 = __shfl_sync(0xffffffffu, p0, 0);
        dsum += p0;
        acc = fmaf(p0, f0, acc);
    }
    float invd = 1.f / fmaxf(dsum, 1e-16f);
    float val = (lane < NCLS) ? acc * invd + __ldg(&b3[lane]) : -1e30f;
    float m = val;
#pragma unroll
    for (int off = 16; off > 0; off >>= 1)
        m = fmaxf(m, __shfl_xor_sync(0xffffffffu, m, off));
    float ex = (lane < NCLS) ? expf(val - m) : 0.f;
    float ssum = ex;
#pragma unroll
    for (int off = 16; off > 0; off >>= 1)
        ssum += __shfl_xor_sync(0xffffffffu, ssum, off);
    float l = m + logf(ssum);
    if (lane < NCLS) out[(size_t)n * NCLS + lane] = val - l;
}

// ---------------- driver -----------------------------------------------------
extern "C" void kernel_launch(void* const* d_in, const int* in_sizes, int n_in,
                              void* d_out, int out_size) {
    const float* x    = (const float*)d_in[0];
    const int*   ei   = (const int*)d_in[1];
    const float* W1   = (const float*)d_in[2];
    const float* a1s  = (const float*)d_in[3];
    const float* a1d  = (const float*)d_in[4];
    const float* b1   = (const float*)d_in[5];
    const float* g1   = (const float*)d_in[6];
    const float* be1  = (const float*)d_in[7];
    const float* W2   = (const float*)d_in[8];
    const float* a2s  = (const float*)d_in[9];
    const float* a2d  = (const float*)d_in[10];
    const float* b2   = (const float*)d_in[11];
    const float* g2   = (const float*)d_in[12];
    const float* be2  = (const float*)d_in[13];
    const float* W3   = (const float*)d_in[14];
    const float* a3s  = (const float*)d_in[15];
    const float* a3d  = (const float*)d_in[16];
    const float* b3   = (const float*)d_in[17];
    float* out = (float*)d_out;

    __half* bufH;
    float *bufA, *bufB, *als, *ald;
    int *deg, *rowptr, *cursor, *bsum, *boff, *csr;
    cudaGetSymbolAddress((void**)&bufH, g_bufH);
    cudaGetSymbolAddress((void**)&bufA, g_bufA);
    cudaGetSymbolAddress((void**)&bufB, g_bufB);
    cudaGetSymbolAddress((void**)&als, g_als);
    cudaGetSymbolAddress((void**)&ald, g_ald);
    cudaGetSymbolAddress((void**)&deg, g_deg);
    cudaGetSymbolAddress((void**)&rowptr, g_rowptr);
    cudaGetSymbolAddress((void**)&cursor, g_cursor);
    cudaGetSymbolAddress((void**)&bsum, g_bsum);
    cudaGetSymbolAddress((void**)&boff, g_boff);
    cudaGetSymbolAddress((void**)&csr, g_csr);

    cudaFuncSetAttribute(gemm_tc, cudaFuncAttributeMaxDynamicSharedMemorySize, GSMEM);

    const int TB = 256;
    const int NB_SCAN = cdiv(NN, SCAN_ELEMS);
    const int NGRID = cdiv(NN, TM);

    // launches 0-2: CSR prep; launch 3 = gemm_tc (ncu capture idx 3)
    fill_i<<<cdiv(NN, TB), TB>>>(deg, 0, NN);
    hist_dst<<<cdiv(ET, TB), TB>>>(ei, deg);
    scan_s1<<<NB_SCAN, 256>>>(deg, bsum);

    gemm_tc<<<NGRID, 256, GSMEM>>>(x, W1, bufH, a1s, a1d, als, ald, NN, F_IN);

    scan_s2<<<1, 256>>>(bsum, boff, NB_SCAN);
    scan_s3<<<NB_SCAN, 256>>>(deg, boff, rowptr, cursor);
    csr_scatter<<<cdiv(ET, TB), TB>>>(ei, cursor, csr);

    // ---- layer 1 rest ----
    aggregate_fused<<<NN, 128>>>(csr, rowptr, deg, als, ald, bufH, b1, g1, be1, bufB);

    // ---- layer 2 ----
    gemm_tc<<<NGRID, 256, GSMEM>>>(bufB, W2, bufH, a2s, a2d, als, ald, NN, F1);
    aggregate_fused<<<NN, 128>>>(csr, rowptr, deg, als, ald, bufH, b2, g2, be2, bufB);

    // ---- layer 3 ----
    gemm10_alpha<<<cdiv(NN * 32, TB), TB>>>(bufB, W3, a3s, a3d, bufA, als, ald);
    aggregate10_lsm<<<cdiv(NN * 32, 128), 128>>>(csr, rowptr, deg, als, ald, bufA, b3, out);
}

// round 12
// speedup vs baseline: 1.1055x; 1.0431x over previous
#include <cuda_runtime.h>
#include <cuda_fp16.h>
#include <math.h>
#include <stdint.h>

#define NN 100000
#define EE 1600000
#define ET (EE + NN)
#define F_IN 500
#define HID 16
#define HEADS 8
#define F1 (HEADS * HID)   // 128
#define NCLS 10

// ---------------- scratch (static device globals) ---------------------------
__device__ __half g_bufH[(size_t)NN * F1];   // fp16 features (gemm output)
__device__ float  g_bufA[(size_t)NN * F1];   // fp32 (layer-3 gemm out)
__device__ float  g_bufB[(size_t)NN * F1];   // fp32 aggregate output
__device__ float  g_als[(size_t)NN * HEADS];
__device__ float  g_ald[(size_t)NN * HEADS];
__device__ int    g_deg[NN];
__device__ int    g_rowptr[NN];
__device__ int    g_cursor[NN];
__device__ int    g_bsum[256];
__device__ int    g_boff[256];
__device__ int    g_csr[(size_t)ET];         // src node per CSR slot

static inline int cdiv(int a, int b) { return (a + b - 1) / b; }

__device__ __forceinline__ uint32_t smem_u32(const void* p) {
    uint32_t a;
    asm("{ .reg .u64 t; cvta.to.shared.u64 t, %1; cvt.u32.u64 %0, t; }"
        : "=r"(a) : "l"(p));
    return a;
}

// ---------------- tiny utils -------------------------------------------------
__global__ void fill_i(int* p, int v, int n) {
    int i = blockIdx.x * blockDim.x + threadIdx.x;
    if (i < n) p[i] = v;
}

// ---------------- CSR build --------------------------------------------------
__global__ void hist_dst(const int* __restrict__ ei, int* __restrict__ deg) {
    int e = blockIdx.x * blockDim.x + threadIdx.x;
    if (e >= ET) return;
    int dst = (e < EE) ? ei[EE + e] : (e - EE);
    atomicAdd(&deg[dst], 1);
}

#define SCAN_ELEMS 512
__global__ void scan_s1(const int* __restrict__ deg, int* __restrict__ bsum) {
    __shared__ int sm[256];
    int base = blockIdx.x * SCAN_ELEMS;
    int t = threadIdx.x;
    int i0 = base + 2 * t, i1 = base + 2 * t + 1;
    int v = 0;
    if (i0 < NN) v += deg[i0];
    if (i1 < NN) v += deg[i1];
    sm[t] = v;
    __syncthreads();
    for (int off = 128; off > 0; off >>= 1) {
        if (t < off) sm[t] += sm[t + off];
        __syncthreads();
    }
    if (t == 0) bsum[blockIdx.x] = sm[0];
}
__global__ void scan_s2(const int* __restrict__ bsum, int* __restrict__ boff, int nb) {
    __shared__ int sm[256];
    int t = threadIdx.x;
    int v = (t < nb) ? bsum[t] : 0;
    sm[t] = v;
    __syncthreads();
    for (int off = 1; off < 256; off <<= 1) {
        int add = (t >= off) ? sm[t - off] : 0;
        __syncthreads();
        sm[t] += add;
        __syncthreads();
    }
    if (t < nb) boff[t] = sm[t] - v;   // exclusive
}
__global__ void scan_s3(const int* __restrict__ deg, const int* __restrict__ boff,
                        int* __restrict__ rowptr, int* __restrict__ cursor) {
    __shared__ int sm[256];
    int base = blockIdx.x * SCAN_ELEMS;
    int t = threadIdx.x;
    int i0 = base + 2 * t, i1 = base + 2 * t + 1;
    int v0 = (i0 < NN) ? deg[i0] : 0;
    int v1 = (i1 < NN) ? deg[i1] : 0;
    int s = v0 + v1;
    sm[t] = s;
    __syncthreads();
    for (int off = 1; off < 256; off <<= 1) {
        int add = (t >= off) ? sm[t - off] : 0;
        __syncthreads();
        sm[t] += add;
        __syncthreads();
    }
    int ex = sm[t] - s + boff[blockIdx.x];
    if (i0 < NN) { rowptr[i0] = ex;      cursor[i0] = ex; }
    if (i1 < NN) { rowptr[i1] = ex + v0; cursor[i1] = ex + v0; }
}

__global__ void csr_scatter(const int* __restrict__ ei, int* __restrict__ cursor,
                            int* __restrict__ csr) {
    int e = blockIdx.x * blockDim.x + threadIdx.x;
    if (e >= ET) return;
    int src, dst;
    if (e < EE) { src = ei[e]; dst = ei[EE + e]; }
    else        { src = dst = e - EE; }
    int pos = atomicAdd(&cursor[dst], 1);
    csr[pos] = src;
}

// ======== tf32 mma.sync GEMM + fused alpha epilogue =========================
#define TM 256
#define KCH 16
#define ASTR 20
#define BSTR 136
#define ABYTES (TM * ASTR * 4)
#define BBYTES (KCH * BSTR * 4)
#define STAGEB (ABYTES + BBYTES)
#define GSMEM (2 * STAGEB)

__global__ __launch_bounds__(256) void gemm_tc(const float* __restrict__ A,
                                               const float* __restrict__ B,
                                               __half* __restrict__ H,
                                               const float* __restrict__ a_src,
                                               const float* __restrict__ a_dst,
                                               float* __restrict__ als,
                                               float* __restrict__ ald,
                                               int M, int K) {
    extern __shared__ float smf[];
    __shared__ float s_as[F1], s_ad[F1];
    uint32_t sbase = smem_u32(smf);
    int tid = threadIdx.x, lane = tid & 31, wid = tid >> 5;
    int wm = (wid & 3) * 64, wn = (wid >> 2) * 64;
    int row0 = blockIdx.x * TM;
    int gid = lane >> 2, tk = lane & 3;
    int niter = (K + KCH - 1) / KCH;

    if (tid < F1) s_as[tid] = a_src[tid];
    else if (tid < 2 * F1) s_ad[tid - F1] = a_dst[tid - F1];

    float acc[4][8][4];
#pragma unroll
    for (int mi = 0; mi < 4; mi++)
#pragma unroll
        for (int ni = 0; ni < 8; ni++)
#pragma unroll
            for (int q = 0; q < 4; q++) acc[mi][ni][q] = 0.f;

    auto load_stage = [&](int s, int k0) {
        uint32_t aB = sbase + s * STAGEB;
        uint32_t bB = aB + ABYTES;
#pragma unroll
        for (int i = 0; i < 4; i++) {
            int id = tid + i * 256;
            int r = id >> 2, c4 = id & 3;
            int gk = k0 + c4 * 4;
            const float* gp = A + (size_t)(row0 + r) * K + gk;
            int remain = K - gk;
            int bytes = 16;
            if (row0 + r >= M || remain <= 0) bytes = 0;
            else if (remain < 4) bytes = remain * 4;
            uint32_t dst = aB + (uint32_t)(r * ASTR + c4 * 4) * 4u;
            asm volatile("cp.async.ca.shared.global [%0], [%1], 16, %2;"
                         :: "r"(dst), "l"(gp), "r"(bytes));
        }
#pragma unroll
        for (int i = 0; i < 2; i++) {
            int id = tid + i * 256;
            int k = id >> 5, c4 = id & 31;
            const float* gp = B + (size_t)(k0 + k) * 128 + c4 * 4;
            int bytes = (k0 + k < K) ? 16 : 0;
            uint32_t dst = bB + (uint32_t)(k * BSTR + c4 * 4) * 4u;
            asm volatile("cp.async.ca.shared.global [%0], [%1], 16, %2;"
                         :: "r"(dst), "l"(gp), "r"(bytes));
        }
        asm volatile("cp.async.commit_group;");
    };

    load_stage(0, 0);

    for (int it = 0; it < niter; it++) {
        if (it + 1 < niter) {
            load_stage((it + 1) & 1, (it + 1) * KCH);
            asm volatile("cp.async.wait_group 1;");
        } else {
            asm volatile("cp.async.wait_group 0;");
        }
        __syncthreads();
        const float* As = smf + ((it & 1) * STAGEB) / 4;
        const float* Bs = As + ABYTES / 4;
#pragma unroll
        for (int ks = 0; ks < 2; ks++) {
            int kb = ks * 8;
            uint32_t af[4][4];
#pragma unroll
            for (int mi = 0; mi < 4; mi++) {
                int r = wm + mi * 16 + gid;
                af[mi][0] = __float_as_uint(As[r * ASTR + kb + tk]);
                af[mi][1] = __float_as_uint(As[(r + 8) * ASTR + kb + tk]);
                af[mi][2] = __float_as_uint(As[r * ASTR + kb + tk + 4]);
                af[mi][3] = __float_as_uint(As[(r + 8) * ASTR + kb + tk + 4]);
            }
            uint32_t bf[8][2];
#pragma unroll
            for (int ni = 0; ni < 8; ni++) {
                int c = wn + ni * 8 + gid;
                bf[ni][0] = __float_as_uint(Bs[(kb + tk) * BSTR + c]);
                bf[ni][1] = __float_as_uint(Bs[(kb + tk + 4) * BSTR + c]);
            }
#pragma unroll
            for (int mi = 0; mi < 4; mi++)
#pragma unroll
                for (int ni = 0; ni < 8; ni++) {
                    asm volatile(
                        "mma.sync.aligned.m16n8k8.row.col.f32.tf32.tf32.f32 "
                        "{%0,%1,%2,%3}, {%4,%5,%6,%7}, {%8,%9}, {%0,%1,%2,%3};"
                        : "+f"(acc[mi][ni][0]), "+f"(acc[mi][ni][1]),
                          "+f"(acc[mi][ni][2]), "+f"(acc[mi][ni][3])
                        : "r"(af[mi][0]), "r"(af[mi][1]), "r"(af[mi][2]), "r"(af[mi][3]),
                          "r"(bf[ni][0]), "r"(bf[ni][1]));
                }
        }
        __syncthreads();
    }

    // ---- fused alpha epilogue ----
#pragma unroll
    for (int mi = 0; mi < 4; mi++) {
#pragma unroll
        for (int half = 0; half < 2; half++) {
            int row = row0 + wm + mi * 16 + half * 8 + gid;
#pragma unroll
            for (int hl = 0; hl < 4; hl++) {
                float ps = 0.f, pd = 0.f;
#pragma unroll
                for (int nj = 0; nj < 2; nj++) {
                    int ni = hl * 2 + nj;
                    int c0 = wn + ni * 8 + tk * 2;
                    float q0 = acc[mi][ni][half * 2 + 0];
                    float q1 = acc[mi][ni][half * 2 + 1];
                    ps += q0 * s_as[c0] + q1 * s_as[c0 + 1];
                    pd += q0 * s_ad[c0] + q1 * s_ad[c0 + 1];
                }
                ps += __shfl_xor_sync(0xffffffffu, ps, 1);
                ps += __shfl_xor_sync(0xffffffffu, ps, 2);
                pd += __shfl_xor_sync(0xffffffffu, pd, 1);
                pd += __shfl_xor_sync(0xffffffffu, pd, 2);
                if (tk == 0 && row < M) {
                    int h = (wn >> 4) + hl;
                    als[(size_t)row * HEADS + h] = ps;
                    ald[(size_t)row * HEADS + h] = pd;
                }
            }
        }
    }

    // ---- fp16 feature store ----
#pragma unroll
    for (int mi = 0; mi < 4; mi++) {
        int r0 = row0 + wm + mi * 16 + gid;
        int r1 = r0 + 8;
#pragma unroll
        for (int ni = 0; ni < 8; ni++) {
            int c = wn + ni * 8 + tk * 2;
            if (r0 < M)
                *(__half2*)(H + (size_t)r0 * 128 + c) =
                    __floats2half2_rn(acc[mi][ni][0], acc[mi][ni][1]);
            if (r1 < M)
                *(__half2*)(H + (size_t)r1 * 128 + c) =
                    __floats2half2_rn(acc[mi][ni][2], acc[mi][ni][3]);
        }
    }
}

// ---------------- fused aggregation (layers 1,2) -----------------------------
__global__ __launch_bounds__(128) void aggregate_fused(
    const int* __restrict__ csr, const int* __restrict__ rowptr,
    const int* __restrict__ deg, const float* __restrict__ als,
    const float* __restrict__ ald, const __half* __restrict__ hfeat,
    const float* __restrict__ bias, const float* __restrict__ gamma,
    const float* __restrict__ beta, float* __restrict__ out) {
    __shared__ float4 s_acc[3][32];
    __shared__ float  s_d[4][8];
    int n = blockIdx.x;
    int t = threadIdx.x;
    int w = t >> 5, l = t & 31;
    int h = l >> 2;
    int c0 = l * 4;
    int start = rowptr[n];
    int len = deg[n];
    float myald = __ldg(&ald[(size_t)n * HEADS + h]);

    float4 acc = make_float4(0.f, 0.f, 0.f, 0.f);
    float dsum = 0.f;

    auto edge = [&](int s) {
        const __half2* hp = (const __half2*)(hfeat + (size_t)s * F1) + l * 2;
        __half2 q0 = __ldg(hp);
        __half2 q1 = __ldg(hp + 1);
        float al = __ldg(&als[(size_t)s * HEADS + h]) + myald;
        al = al > 0.f ? al : 0.2f * al;
        float p = __expf(al);
        dsum += p;
        float2 f0 = __half22float2(q0);
        float2 f1 = __half22float2(q1);
        acc.x = fmaf(p, f0.x, acc.x);
        acc.y = fmaf(p, f0.y, acc.y);
        acc.z = fmaf(p, f1.x, acc.z);
        acc.w = fmaf(p, f1.y, acc.w);
    };

    int i = w;
    for (; i + 4 < len; i += 8) {
        int s0 = __ldg(&csr[start + i]);
        int s1 = __ldg(&csr[start + i + 4]);
        edge(s0);
        edge(s1);
    }
    if (i < len) {
        int s0 = __ldg(&csr[start + i]);
        edge(s0);
    }

    if (w > 0) s_acc[w - 1][l] = acc;
    if ((l & 3) == 0) s_d[w][h] = dsum;
    __syncthreads();
    if (w == 0) {
        float4 a1 = s_acc[0][l], a2 = s_acc[1][l], a3 = s_acc[2][l];
        acc.x += a1.x + a2.x + a3.x;
        acc.y += a1.y + a2.y + a3.y;
        acc.z += a1.z + a2.z + a3.z;
        acc.w += a1.w + a2.w + a3.w;
        float dall = s_d[0][h] + s_d[1][h] + s_d[2][h] + s_d[3][h];
        float invd = 1.f / fmaxf(dall, 1e-16f);
        float4 bb = *(const float4*)(bias + c0);
        float4 gg = *(const float4*)(gamma + c0);
        float4 be = *(const float4*)(beta + c0);
        float bnf = rsqrtf(1.0f + 1e-5f);
        float v0 = acc.x * invd + bb.x;
        float v1 = acc.y * invd + bb.y;
        float v2 = acc.z * invd + bb.z;
        float v3 = acc.w * invd + bb.w;
        v0 = v0 > 0.f ? v0 : (__expf(v0) - 1.f);
        v1 = v1 > 0.f ? v1 : (__expf(v1) - 1.f);
        v2 = v2 > 0.f ? v2 : (__expf(v2) - 1.f);
        v3 = v3 > 0.f ? v3 : (__expf(v3) - 1.f);
        float4 r;
        r.x = v0 * gg.x * bnf + be.x;
        r.y = v1 * gg.y * bnf + be.y;
        r.z = v2 * gg.z * bnf + be.z;
        r.w = v3 * gg.w * bnf + be.w;
        *(float4*)(out + (size_t)n * F1 + c0) = r;
    }
}

// ---------------- layer 3: fused GEMM(128->10) + node alphas ----------------
__global__ void gemm10_alpha(const float* __restrict__ A, const float* __restrict__ W,
                             const float* __restrict__ a3s, const float* __restrict__ a3d,
                             float* __restrict__ C, float* __restrict__ als,
                             float* __restrict__ ald) {
    __shared__ float Ws[F1 * NCLS];
    for (int i = threadIdx.x; i < F1 * NCLS; i += blockDim.x) Ws[i] = W[i];
    __syncthreads();
    int warp = (blockIdx.x * blockDim.x + threadIdx.x) >> 5;
    int lane = threadIdx.x & 31;
    if (warp >= NN) return;
    float acc[NCLS];
#pragma unroll
    for (int c = 0; c < NCLS; c++) acc[c] = 0.f;
    const float* arow = A + (size_t)warp * F1;
#pragma unroll
    for (int q = 0; q < 4; q++) {
        int k = lane + q * 32;
        float a = arow[k];
#pragma unroll
        for (int c = 0; c < NCLS; c++) acc[c] += a * Ws[k * NCLS + c];
    }
#pragma unroll
    for (int off = 16; off > 0; off >>= 1)
#pragma unroll
        for (int c = 0; c < NCLS; c++) acc[c] += __shfl_xor_sync(0xffffffffu, acc[c], off);
    if (lane < NCLS) C[(size_t)warp * NCLS + lane] = acc[lane];
    if (lane == 0) {
        float s = 0.f, d = 0.f;
#pragma unroll
        for (int c = 0; c < NCLS; c++) {
            s += acc[c] * __ldg(&a3s[c]);
            d += acc[c] * __ldg(&a3d[c]);
        }
        als[warp] = s;
        ald[warp] = d;
    }
}

// ---------------- layer 3: fused aggregation + bias + log_softmax ------------
__global__ __launch_bounds__(128) void aggregate10_lsm(
    const int* __restrict__ csr, const int* __restrict__ rowptr,
    const int* __restrict__ deg, const float* __restrict__ als,
    const float* __restrict__ ald, const float* __restrict__ hfeat,
    const float* __restrict__ b3, float* __restrict__ out) {
    int warp = (blockIdx.x * blockDim.x + threadIdx.x) >> 5;
    int lane = threadIdx.x & 31;
    if (warp >= NN) return;
    int n = warp;
    int start = rowptr[n];
    int len = deg[n];
    float myald = (lane == 0) ? __ldg(&ald[n]) : 0.f;
    float acc = 0.f, dsum = 0.f;
    int i = 0;
    for (; i + 2 <= len; i += 2) {
        int s0 = __ldg(&csr[start + i]);
        int s1 = __ldg(&csr[start + i + 1]);
        float f0 = (lane < NCLS) ? __ldg(&hfeat[(size_t)s0 * NCLS + lane]) : 0.f;
        float f1 = (lane < NCLS) ? __ldg(&hfeat[(size_t)s1 * NCLS + lane]) : 0.f;
        float p0 = 0.f, p1 = 0.f;
        if (lane == 0) {
            float l0 = __ldg(&als[s0]) + myald;
            float l1 = __ldg(&als[s1]) + myald;
            l0 = l0 > 0.f ? l0 : 0.2f * l0;
            l1 = l1 > 0.f ? l1 : 0.2f * l1;
            p0 = __expf(l0);
            p1 = __expf(l1);
        }
        p0 = __shfl_sync(0xffffffffu, p0, 0);
        p1 = __shfl_sync(0xffffffffu, p1, 0);
        dsum += p0 + p1;
        acc = fmaf(p0, f0, fmaf(p1, f1, acc));
    }
    if (i < len) {
        int s0 = __ldg(&csr[start + i]);
        float f0 = (lane < NCLS) ? __ldg(&hfeat[(size_t)s0 * NCLS + lane]) : 0.f;
        float p0 = 0.f;
        if (lane == 0) {
            float l0 = __ldg(&als[s0]) + myald;
            l0 = l0 > 0.f ? l0 : 0.2f * l0;
            p0 = __expf(l0);
        }
        p0 = __shfl_sync(0xffffffffu, p0, 0);
        dsum += p0;
        acc = fmaf(p0, f0, acc);
    }
    float invd = 1.f / fmaxf(dsum, 1e-16f);
    float val = (lane < NCLS) ? acc * invd + __ldg(&b3[lane]) : -1e30f;
    float m = val;
#pragma unroll
    for (int off = 16; off > 0; off >>= 1)
        m = fmaxf(m, __shfl_xor_sync(0xffffffffu, m, off));
    float ex = (lane < NCLS) ? expf(val - m) : 0.f;
    float ssum = ex;
#pragma unroll
    for (int off = 16; off > 0; off >>= 1)
        ssum += __shfl_xor_sync(0xffffffffu, ssum, off);
    float l = m + logf(ssum);
    if (lane < NCLS) out[(size_t)n * NCLS + lane] = val - l;
}

// ---------------- driver -----------------------------------------------------
extern "C" void kernel_launch(void* const* d_in, const int* in_sizes, int n_in,
                              void* d_out, int out_size) {
    const float* x    = (const float*)d_in[0];
    const int*   ei   = (const int*)d_in[1];
    const float* W1   = (const float*)d_in[2];
    const float* a1s  = (const float*)d_in[3];
    const float* a1d  = (const float*)d_in[4];
    const float* b1   = (const float*)d_in[5];
    const float* g1   = (const float*)d_in[6];
    const float* be1  = (const float*)d_in[7];
    const float* W2   = (const float*)d_in[8];
    const float* a2s  = (const float*)d_in[9];
    const float* a2d  = (const float*)d_in[10];
    const float* b2   = (const float*)d_in[11];
    const float* g2   = (const float*)d_in[12];
    const float* be2  = (const float*)d_in[13];
    const float* W3   = (const float*)d_in[14];
    const float* a3s  = (const float*)d_in[15];
    const float* a3d  = (const float*)d_in[16];
    const float* b3   = (const float*)d_in[17];
    float* out = (float*)d_out;

    __half* bufH;
    float *bufA, *bufB, *als, *ald;
    int *deg, *rowptr, *cursor, *bsum, *boff, *csr;
    cudaGetSymbolAddress((void**)&bufH, g_bufH);
    cudaGetSymbolAddress((void**)&bufA, g_bufA);
    cudaGetSymbolAddress((void**)&bufB, g_bufB);
    cudaGetSymbolAddress((void**)&als, g_als);
    cudaGetSymbolAddress((void**)&ald, g_ald);
    cudaGetSymbolAddress((void**)&deg, g_deg);
    cudaGetSymbolAddress((void**)&rowptr, g_rowptr);
    cudaGetSymbolAddress((void**)&cursor, g_cursor);
    cudaGetSymbolAddress((void**)&bsum, g_bsum);
    cudaGetSymbolAddress((void**)&boff, g_boff);
    cudaGetSymbolAddress((void**)&csr, g_csr);

    cudaFuncSetAttribute(gemm_tc, cudaFuncAttributeMaxDynamicSharedMemorySize, GSMEM);

    // one-time side stream + events (host-side handles; no device memory)
    static cudaStream_t s2 = nullptr;
    static cudaEvent_t evFork = nullptr, evJoin = nullptr;
    if (s2 == nullptr) {
        cudaStreamCreate(&s2);
        cudaEventCreateWithFlags(&evFork, cudaEventDisableTiming);
        cudaEventCreateWithFlags(&evJoin, cudaEventDisableTiming);
    }

    const int TB = 256;
    const int NB_SCAN = cdiv(NN, SCAN_ELEMS);
    const int NGRID = cdiv(NN, TM);

    // ---- fork: CSR build on s2, GEMM1 on main stream, join before aggregate ----
    cudaEventRecord(evFork, 0);
    cudaStreamWaitEvent(s2, evFork, 0);

    fill_i<<<cdiv(NN, TB), TB, 0, s2>>>(deg, 0, NN);
    hist_dst<<<cdiv(ET, TB), TB, 0, s2>>>(ei, deg);
    scan_s1<<<NB_SCAN, 256, 0, s2>>>(deg, bsum);
    scan_s2<<<1, 256, 0, s2>>>(bsum, boff, NB_SCAN);
    scan_s3<<<NB_SCAN, 256, 0, s2>>>(deg, boff, rowptr, cursor);
    csr_scatter<<<cdiv(ET, TB), TB, 0, s2>>>(ei, cursor, csr);
    cudaEventRecord(evJoin, s2);

    gemm_tc<<<NGRID, 256, GSMEM>>>(x, W1, bufH, a1s, a1d, als, ald, NN, F_IN);

    cudaStreamWaitEvent(0, evJoin, 0);

    // ---- layer 1 aggregation ----
    aggregate_fused<<<NN, 128>>>(csr, rowptr, deg, als, ald, bufH, b1, g1, be1, bufB);

    // ---- layer 2 ----
    gemm_tc<<<NGRID, 256, GSMEM>>>(bufB, W2, bufH, a2s, a2d, als, ald, NN, F1);
    aggregate_fused<<<NN, 128>>>(csr, rowptr, deg, als, ald, bufH, b2, g2, be2, bufB);

    // ---- layer 3 ----
    gemm10_alpha<<<cdiv(NN * 32, TB), TB>>>(bufB, W3, a3s, a3d, bufA, als, ald);
    aggregate10_lsm<<<cdiv(NN * 32, 128), 128>>>(csr, rowptr, deg, als, ald, bufA, b3, out);
}

// round 13
// speedup vs baseline: 1.1780x; 1.0655x over previous
#include <cuda_runtime.h>
#include <cuda_fp16.h>
#include <math.h>
#include <stdint.h>

#define NN 100000
#define EE 1600000
#define ET (EE + NN)
#define F_IN 500
#define HID 16
#define HEADS 8
#define F1 (HEADS * HID)   // 128
#define NCLS 10

// ---------------- scratch (static device globals) ---------------------------
__device__ __half g_bufH[(size_t)NN * F1];   // fp16 features (gemm output)
__device__ float  g_bufA[(size_t)NN * F1];   // fp32 (layer-3 gemm out)
__device__ float  g_bufB[(size_t)NN * F1];   // fp32 aggregate output
__device__ float  g_als[(size_t)NN * HEADS];
__device__ float  g_ald[(size_t)NN * HEADS];
__device__ int    g_deg[NN];
__device__ int    g_rowptr[NN];
__device__ int    g_cursor[NN];
__device__ int    g_bsum[256];
__device__ int    g_boff[256];
__device__ int    g_csr[(size_t)ET];         // src node per CSR slot

static inline int cdiv(int a, int b) { return (a + b - 1) / b; }

__device__ __forceinline__ uint32_t smem_u32(const void* p) {
    uint32_t a;
    asm("{ .reg .u64 t; cvta.to.shared.u64 t, %1; cvt.u32.u64 %0, t; }"
        : "=r"(a) : "l"(p));
    return a;
}

// ---------------- tiny utils -------------------------------------------------
__global__ void fill_i(int* p, int v, int n) {
    int i = blockIdx.x * blockDim.x + threadIdx.x;
    if (i < n) p[i] = v;
}

// ---------------- CSR build --------------------------------------------------
__global__ void hist_dst(const int* __restrict__ ei, int* __restrict__ deg) {
    int e = blockIdx.x * blockDim.x + threadIdx.x;
    if (e >= ET) return;
    int dst = (e < EE) ? ei[EE + e] : (e - EE);
    atomicAdd(&deg[dst], 1);
}

#define SCAN_ELEMS 512
__global__ void scan_s1(const int* __restrict__ deg, int* __restrict__ bsum) {
    __shared__ int sm[256];
    int base = blockIdx.x * SCAN_ELEMS;
    int t = threadIdx.x;
    int i0 = base + 2 * t, i1 = base + 2 * t + 1;
    int v = 0;
    if (i0 < NN) v += deg[i0];
    if (i1 < NN) v += deg[i1];
    sm[t] = v;
    __syncthreads();
    for (int off = 128; off > 0; off >>= 1) {
        if (t < off) sm[t] += sm[t + off];
        __syncthreads();
    }
    if (t == 0) bsum[blockIdx.x] = sm[0];
}
__global__ void scan_s2(const int* __restrict__ bsum, int* __restrict__ boff, int nb) {
    __shared__ int sm[256];
    int t = threadIdx.x;
    int v = (t < nb) ? bsum[t] : 0;
    sm[t] = v;
    __syncthreads();
    for (int off = 1; off < 256; off <<= 1) {
        int add = (t >= off) ? sm[t - off] : 0;
        __syncthreads();
        sm[t] += add;
        __syncthreads();
    }
    if (t < nb) boff[t] = sm[t] - v;   // exclusive
}
__global__ void scan_s3(const int* __restrict__ deg, const int* __restrict__ boff,
                        int* __restrict__ rowptr, int* __restrict__ cursor) {
    __shared__ int sm[256];
    int base = blockIdx.x * SCAN_ELEMS;
    int t = threadIdx.x;
    int i0 = base + 2 * t, i1 = base + 2 * t + 1;
    int v0 = (i0 < NN) ? deg[i0] : 0;
    int v1 = (i1 < NN) ? deg[i1] : 0;
    int s = v0 + v1;
    sm[t] = s;
    __syncthreads();
    for (int off = 1; off < 256; off <<= 1) {
        int add = (t >= off) ? sm[t - off] : 0;
        __syncthreads();
        sm[t] += add;
        __syncthreads();
    }
    int ex = sm[t] - s + boff[blockIdx.x];
    if (i0 < NN) { rowptr[i0] = ex;      cursor[i0] = ex; }
    if (i1 < NN) { rowptr[i1] = ex + v0; cursor[i1] = ex + v0; }
}

__global__ void csr_scatter(const int* __restrict__ ei, int* __restrict__ cursor,
                            int* __restrict__ csr) {
    int e = blockIdx.x * blockDim.x + threadIdx.x;
    if (e >= ET) return;
    int src, dst;
    if (e < EE) { src = ei[e]; dst = ei[EE + e]; }
    else        { src = dst = e - EE; }
    int pos = atomicAdd(&cursor[dst], 1);
    csr[pos] = src;
}

// ======== tf32 mma.sync GEMM + fused alpha epilogue =========================
// Block tile 128x128, 4 warps (2x2) of 64x64, 128 threads, 2 CTAs/SM,
// 3-stage cp.async pipeline.
#define TM 128
#define KCH 16
#define ASTR 20
#define BSTR 136
#define ABYTES (TM * ASTR * 4)    // 10240
#define BBYTES (KCH * BSTR * 4)   // 8704
#define STAGEB (ABYTES + BBYTES)  // 18944
#define NSTAGE 3
#define GSMEM (NSTAGE * STAGEB)   // 56832

__global__ __launch_bounds__(128, 2) void gemm_tc(const float* __restrict__ A,
                                                  const float* __restrict__ B,
                                                  __half* __restrict__ H,
                                                  const float* __restrict__ a_src,
                                                  const float* __restrict__ a_dst,
                                                  float* __restrict__ als,
                                                  float* __restrict__ ald,
                                                  int M, int K) {
    extern __shared__ float smf[];
    __shared__ float s_as[F1], s_ad[F1];
    uint32_t sbase = smem_u32(smf);
    int tid = threadIdx.x, lane = tid & 31, wid = tid >> 5;
    int wm = (wid & 1) * 64, wn = (wid >> 1) * 64;
    int row0 = blockIdx.x * TM;
    int gid = lane >> 2, tk = lane & 3;
    int niter = (K + KCH - 1) / KCH;

    s_as[tid] = a_src[tid];
    s_ad[tid] = a_dst[tid];

    float acc[4][8][4];
#pragma unroll
    for (int mi = 0; mi < 4; mi++)
#pragma unroll
        for (int ni = 0; ni < 8; ni++)
#pragma unroll
            for (int q = 0; q < 4; q++) acc[mi][ni][q] = 0.f;

    auto load_stage = [&](int s, int k0) {
        uint32_t aB = sbase + s * STAGEB;
        uint32_t bB = aB + ABYTES;
#pragma unroll
        for (int i = 0; i < 4; i++) {
            int id = tid + i * 128;          // 512 chunks: A 128 rows x 4
            int r = id >> 2, c4 = id & 3;
            int gk = k0 + c4 * 4;
            const float* gp = A + (size_t)(row0 + r) * K + gk;
            int remain = K - gk;
            int bytes = 16;
            if (row0 + r >= M || remain <= 0) bytes = 0;
            else if (remain < 4) bytes = remain * 4;
            uint32_t dst = aB + (uint32_t)(r * ASTR + c4 * 4) * 4u;
            asm volatile("cp.async.ca.shared.global [%0], [%1], 16, %2;"
                         :: "r"(dst), "l"(gp), "r"(bytes));
        }
#pragma unroll
        for (int i = 0; i < 4; i++) {
            int id = tid + i * 128;          // 512 chunks: B 16 rows x 32
            int k = id >> 5, c4 = id & 31;
            const float* gp = B + (size_t)(k0 + k) * 128 + c4 * 4;
            int bytes = (k0 + k < K) ? 16 : 0;
            uint32_t dst = bB + (uint32_t)(k * BSTR + c4 * 4) * 4u;
            asm volatile("cp.async.ca.shared.global [%0], [%1], 16, %2;"
                         :: "r"(dst), "l"(gp), "r"(bytes));
        }
        asm volatile("cp.async.commit_group;");
    };

    load_stage(0, 0);
    if (niter > 1) load_stage(1, KCH);

    for (int it = 0; it < niter; it++) {
        if (it + 1 < niter) asm volatile("cp.async.wait_group 1;");
        else                asm volatile("cp.async.wait_group 0;");
        __syncthreads();
        if (it + 2 < niter) load_stage((it + 2) % NSTAGE, (it + 2) * KCH);

        const float* As = smf + ((it % NSTAGE) * STAGEB) / 4;
        const float* Bs = As + ABYTES / 4;
#pragma unroll
        for (int ks = 0; ks < 2; ks++) {
            int kb = ks * 8;
            uint32_t af[4][4];
#pragma unroll
            for (int mi = 0; mi < 4; mi++) {
                int r = wm + mi * 16 + gid;
                af[mi][0] = __float_as_uint(As[r * ASTR + kb + tk]);
                af[mi][1] = __float_as_uint(As[(r + 8) * ASTR + kb + tk]);
                af[mi][2] = __float_as_uint(As[r * ASTR + kb + tk + 4]);
                af[mi][3] = __float_as_uint(As[(r + 8) * ASTR + kb + tk + 4]);
            }
            uint32_t bf[8][2];
#pragma unroll
            for (int ni = 0; ni < 8; ni++) {
                int c = wn + ni * 8 + gid;
                bf[ni][0] = __float_as_uint(Bs[(kb + tk) * BSTR + c]);
                bf[ni][1] = __float_as_uint(Bs[(kb + tk + 4) * BSTR + c]);
            }
#pragma unroll
            for (int mi = 0; mi < 4; mi++)
#pragma unroll
                for (int ni = 0; ni < 8; ni++) {
                    asm volatile(
                        "mma.sync.aligned.m16n8k8.row.col.f32.tf32.tf32.f32 "
                        "{%0,%1,%2,%3}, {%4,%5,%6,%7}, {%8,%9}, {%0,%1,%2,%3};"
                        : "+f"(acc[mi][ni][0]), "+f"(acc[mi][ni][1]),
                          "+f"(acc[mi][ni][2]), "+f"(acc[mi][ni][3])
                        : "r"(af[mi][0]), "r"(af[mi][1]), "r"(af[mi][2]), "r"(af[mi][3]),
                          "r"(bf[ni][0]), "r"(bf[ni][1]));
                }
        }
        __syncthreads();
    }

    // ---- fused alpha epilogue ----
#pragma unroll
    for (int mi = 0; mi < 4; mi++) {
#pragma unroll
        for (int half = 0; half < 2; half++) {
            int row = row0 + wm + mi * 16 + half * 8 + gid;
#pragma unroll
            for (int hl = 0; hl < 4; hl++) {
                float ps = 0.f, pd = 0.f;
#pragma unroll
                for (int nj = 0; nj < 2; nj++) {
                    int ni = hl * 2 + nj;
                    int c0 = wn + ni * 8 + tk * 2;
                    float q0 = acc[mi][ni][half * 2 + 0];
                    float q1 = acc[mi][ni][half * 2 + 1];
                    ps += q0 * s_as[c0] + q1 * s_as[c0 + 1];
                    pd += q0 * s_ad[c0] + q1 * s_ad[c0 + 1];
                }
                ps += __shfl_xor_sync(0xffffffffu, ps, 1);
                ps += __shfl_xor_sync(0xffffffffu, ps, 2);
                pd += __shfl_xor_sync(0xffffffffu, pd, 1);
                pd += __shfl_xor_sync(0xffffffffu, pd, 2);
                if (tk == 0 && row < M) {
                    int h = (wn >> 4) + hl;
                    als[(size_t)row * HEADS + h] = ps;
                    ald[(size_t)row * HEADS + h] = pd;
                }
            }
        }
    }

    // ---- fp16 feature store ----
#pragma unroll
    for (int mi = 0; mi < 4; mi++) {
        int r0 = row0 + wm + mi * 16 + gid;
        int r1 = r0 + 8;
#pragma unroll
        for (int ni = 0; ni < 8; ni++) {
            int c = wn + ni * 8 + tk * 2;
            if (r0 < M)
                *(__half2*)(H + (size_t)r0 * 128 + c) =
                    __floats2half2_rn(acc[mi][ni][0], acc[mi][ni][1]);
            if (r1 < M)
                *(__half2*)(H + (size_t)r1 * 128 + c) =
                    __floats2half2_rn(acc[mi][ni][2], acc[mi][ni][3]);
        }
    }
}

// ---------------- fused aggregation (layers 1,2) -----------------------------
__global__ __launch_bounds__(128) void aggregate_fused(
    const int* __restrict__ csr, const int* __restrict__ rowptr,
    const int* __restrict__ deg, const float* __restrict__ als,
    const float* __restrict__ ald, const __half* __restrict__ hfeat,
    const float* __restrict__ bias, const float* __restrict__ gamma,
    const float* __restrict__ beta, float* __restrict__ out) {
    __shared__ float4 s_acc[3][32];
    __shared__ float  s_d[4][8];
    int n = blockIdx.x;
    int t = threadIdx.x;
    int w = t >> 5, l = t & 31;
    int h = l >> 2;
    int c0 = l * 4;
    int start = rowptr[n];
    int len = deg[n];
    float myald = __ldg(&ald[(size_t)n * HEADS + h]);

    float4 acc = make_float4(0.f, 0.f, 0.f, 0.f);
    float dsum = 0.f;

    auto edge = [&](int s) {
        const __half2* hp = (const __half2*)(hfeat + (size_t)s * F1) + l * 2;
        __half2 q0 = __ldg(hp);
        __half2 q1 = __ldg(hp + 1);
        float al = __ldg(&als[(size_t)s * HEADS + h]) + myald;
        al = al > 0.f ? al : 0.2f * al;
        float p = __expf(al);
        dsum += p;
        float2 f0 = __half22float2(q0);
        float2 f1 = __half22float2(q1);
        acc.x = fmaf(p, f0.x, acc.x);
        acc.y = fmaf(p, f0.y, acc.y);
        acc.z = fmaf(p, f1.x, acc.z);
        acc.w = fmaf(p, f1.y, acc.w);
    };

    int i = w;
    for (; i + 4 < len; i += 8) {
        int s0 = __ldg(&csr[start + i]);
        int s1 = __ldg(&csr[start + i + 4]);
        edge(s0);
        edge(s1);
    }
    if (i < len) {
        int s0 = __ldg(&csr[start + i]);
        edge(s0);
    }

    if (w > 0) s_acc[w - 1][l] = acc;
    if ((l & 3) == 0) s_d[w][h] = dsum;
    __syncthreads();
    if (w == 0) {
        float4 a1 = s_acc[0][l], a2 = s_acc[1][l], a3 = s_acc[2][l];
        acc.x += a1.x + a2.x + a3.x;
        acc.y += a1.y + a2.y + a3.y;
        acc.z += a1.z + a2.z + a3.z;
        acc.w += a1.w + a2.w + a3.w;
        float dall = s_d[0][h] + s_d[1][h] + s_d[2][h] + s_d[3][h];
        float invd = 1.f / fmaxf(dall, 1e-16f);
        float4 bb = *(const float4*)(bias + c0);
        float4 gg = *(const float4*)(gamma + c0);
        float4 be = *(const float4*)(beta + c0);
        float bnf = rsqrtf(1.0f + 1e-5f);
        float v0 = acc.x * invd + bb.x;
        float v1 = acc.y * invd + bb.y;
        float v2 = acc.z * invd + bb.z;
        float v3 = acc.w * invd + bb.w;
        v0 = v0 > 0.f ? v0 : (__expf(v0) - 1.f);
        v1 = v1 > 0.f ? v1 : (__expf(v1) - 1.f);
        v2 = v2 > 0.f ? v2 : (__expf(v2) - 1.f);
        v3 = v3 > 0.f ? v3 : (__expf(v3) - 1.f);
        float4 r;
        r.x = v0 * gg.x * bnf + be.x;
        r.y = v1 * gg.y * bnf + be.y;
        r.z = v2 * gg.z * bnf + be.z;
        r.w = v3 * gg.w * bnf + be.w;
        *(float4*)(out + (size_t)n * F1 + c0) = r;
    }
}

// ---------------- layer 3: fused GEMM(128->10) + node alphas ----------------
__global__ void gemm10_alpha(const float* __restrict__ A, const float* __restrict__ W,
                             const float* __restrict__ a3s, const float* __restrict__ a3d,
                             float* __restrict__ C, float* __restrict__ als,
                             float* __restrict__ ald) {
    __shared__ float Ws[F1 * NCLS];
    for (int i = threadIdx.x; i < F1 * NCLS; i += blockDim.x) Ws[i] = W[i];
    __syncthreads();
    int warp = (blockIdx.x * blockDim.x + threadIdx.x) >> 5;
    int lane = threadIdx.x & 31;
    if (warp >= NN) return;
    float acc[NCLS];
#pragma unroll
    for (int c = 0; c < NCLS; c++) acc[c] = 0.f;
    const float* arow = A + (size_t)warp * F1;
#pragma unroll
    for (int q = 0; q < 4; q++) {
        int k = lane + q * 32;
        float a = arow[k];
#pragma unroll
        for (int c = 0; c < NCLS; c++) acc[c] += a * Ws[k * NCLS + c];
    }
#pragma unroll
    for (int off = 16; off > 0; off >>= 1)
#pragma unroll
        for (int c = 0; c < NCLS; c++) acc[c] += __shfl_xor_sync(0xffffffffu, acc[c], off);
    if (lane < NCLS) C[(size_t)warp * NCLS + lane] = acc[lane];
    if (lane == 0) {
        float s = 0.f, d = 0.f;
#pragma unroll
        for (int c = 0; c < NCLS; c++) {
            s += acc[c] * __ldg(&a3s[c]);
            d += acc[c] * __ldg(&a3d[c]);
        }
        als[warp] = s;
        ald[warp] = d;
    }
}

// ---------------- layer 3: fused aggregation + bias + log_softmax ------------
__global__ __launch_bounds__(128) void aggregate10_lsm(
    const int* __restrict__ csr, const int* __restrict__ rowptr,
    const int* __restrict__ deg, const float* __restrict__ als,
    const float* __restrict__ ald, const float* __restrict__ hfeat,
    const float* __restrict__ b3, float* __restrict__ out) {
    int warp = (blockIdx.x * blockDim.x + threadIdx.x) >> 5;
    int lane = threadIdx.x & 31;
    if (warp >= NN) return;
    int n = warp;
    int start = rowptr[n];
    int len = deg[n];
    float myald = (lane == 0) ? __ldg(&ald[n]) : 0.f;
    float acc = 0.f, dsum = 0.f;
    int i = 0;
    for (; i + 2 <= len; i += 2) {
        int s0 = __ldg(&csr[start + i]);
        int s1 = __ldg(&csr[start + i + 1]);
        float f0 = (lane < NCLS) ? __ldg(&hfeat[(size_t)s0 * NCLS + lane]) : 0.f;
        float f1 = (lane < NCLS) ? __ldg(&hfeat[(size_t)s1 * NCLS + lane]) : 0.f;
        float p0 = 0.f, p1 = 0.f;
        if (lane == 0) {
            float l0 = __ldg(&als[s0]) + myald;
            float l1 = __ldg(&als[s1]) + myald;
            l0 = l0 > 0.f ? l0 : 0.2f * l0;
            l1 = l1 > 0.f ? l1 : 0.2f * l1;
            p0 = __expf(l0);
            p1 = __expf(l1);
        }
        p0 = __shfl_sync(0xffffffffu, p0, 0);
        p1 = __shfl_sync(0xffffffffu, p1, 0);
        dsum += p0 + p1;
        acc = fmaf(p0, f0, fmaf(p1, f1, acc));
    }
    if (i < len) {
        int s0 = __ldg(&csr[start + i]);
        float f0 = (lane < NCLS) ? __ldg(&hfeat[(size_t)s0 * NCLS + lane]) : 0.f;
        float p0 = 0.f;
        if (lane == 0) {
            float l0 = __ldg(&als[s0]) + myald;
            l0 = l0 > 0.f ? l0 : 0.2f * l0;
            p0 = __expf(l0);
        }
        p0 = __shfl_sync(0xffffffffu, p0, 0);
        dsum += p0;
        acc = fmaf(p0, f0, acc);
    }
    float invd = 1.f / fmaxf(dsum, 1e-16f);
    float val = (lane < NCLS) ? acc * invd + __ldg(&b3[lane]) : -1e30f;
    float m = val;
#pragma unroll
    for (int off = 16; off > 0; off >>= 1)
        m = fmaxf(m, __shfl_xor_sync(0xffffffffu, m, off));
    float ex = (lane < NCLS) ? expf(val - m) : 0.f;
    float ssum = ex;
#pragma unroll
    for (int off = 16; off > 0; off >>= 1)
        ssum += __shfl_xor_sync(0xffffffffu, ssum, off);
    float l = m + logf(ssum);
    if (lane < NCLS) out[(size_t)n * NCLS + lane] = val - l;
}

// ---------------- driver -----------------------------------------------------
extern "C" void kernel_launch(void* const* d_in, const int* in_sizes, int n_in,
                              void* d_out, int out_size) {
    const float* x    = (const float*)d_in[0];
    const int*   ei   = (const int*)d_in[1];
    const float* W1   = (const float*)d_in[2];
    const float* a1s  = (const float*)d_in[3];
    const float* a1d  = (const float*)d_in[4];
    const float* b1   = (const float*)d_in[5];
    const float* g1   = (const float*)d_in[6];
    const float* be1  = (const float*)d_in[7];
    const float* W2   = (const float*)d_in[8];
    const float* a2s  = (const float*)d_in[9];
    const float* a2d  = (const float*)d_in[10];
    const float* b2   = (const float*)d_in[11];
    const float* g2   = (const float*)d_in[12];
    const float* be2  = (const float*)d_in[13];
    const float* W3   = (const float*)d_in[14];
    const float* a3s  = (const float*)d_in[15];
    const float* a3d  = (const float*)d_in[16];
    const float* b3   = (const float*)d_in[17];
    float* out = (float*)d_out;

    __half* bufH;
    float *bufA, *bufB, *als, *ald;
    int *deg, *rowptr, *cursor, *bsum, *boff, *csr;
    cudaGetSymbolAddress((void**)&bufH, g_bufH);
    cudaGetSymbolAddress((void**)&bufA, g_bufA);
    cudaGetSymbolAddress((void**)&bufB, g_bufB);
    cudaGetSymbolAddress((void**)&als, g_als);
    cudaGetSymbolAddress((void**)&ald, g_ald);
    cudaGetSymbolAddress((void**)&deg, g_deg);
    cudaGetSymbolAddress((void**)&rowptr, g_rowptr);
    cudaGetSymbolAddress((void**)&cursor, g_cursor);
    cudaGetSymbolAddress((void**)&bsum, g_bsum);
    cudaGetSymbolAddress((void**)&boff, g_boff);
    cudaGetSymbolAddress((void**)&csr, g_csr);

    cudaFuncSetAttribute(gemm_tc, cudaFuncAttributeMaxDynamicSharedMemorySize, GSMEM);

    // one-time side stream + events (host-side handles; no device memory)
    static cudaStream_t s2 = nullptr;
    static cudaEvent_t evFork = nullptr, evJoin = nullptr;
    if (s2 == nullptr) {
        cudaStreamCreate(&s2);
        cudaEventCreateWithFlags(&evFork, cudaEventDisableTiming);
        cudaEventCreateWithFlags(&evJoin, cudaEventDisableTiming);
    }

    const int TB = 256;
    const int NB_SCAN = cdiv(NN, SCAN_ELEMS);
    const int NGRID = cdiv(NN, TM);

    // ---- fork: CSR build on s2, GEMM1 on main stream, join before aggregate ----
    cudaEventRecord(evFork, 0);
    cudaStreamWaitEvent(s2, evFork, 0);

    fill_i<<<cdiv(NN, TB), TB, 0, s2>>>(deg, 0, NN);
    hist_dst<<<cdiv(ET, TB), TB, 0, s2>>>(ei, deg);
    scan_s1<<<NB_SCAN, 256, 0, s2>>>(deg, bsum);
    scan_s2<<<1, 256, 0, s2>>>(bsum, boff, NB_SCAN);
    scan_s3<<<NB_SCAN, 256, 0, s2>>>(deg, boff, rowptr, cursor);
    csr_scatter<<<cdiv(ET, TB), TB, 0, s2>>>(ei, cursor, csr);
    cudaEventRecord(evJoin, s2);

    gemm_tc<<<NGRID, 128, GSMEM>>>(x, W1, bufH, a1s, a1d, als, ald, NN, F_IN);

    cudaStreamWaitEvent(0, evJoin, 0);

    // ---- layer 1 aggregation ----
    aggregate_fused<<<NN, 128>>>(csr, rowptr, deg, als, ald, bufH, b1, g1, be1, bufB);

    // ---- layer 2 ----
    gemm_tc<<<NGRID, 128, GSMEM>>>(bufB, W2, bufH, a2s, a2d, als, ald, NN, F1);
    aggregate_fused<<<NN, 128>>>(csr, rowptr, deg, als, ald, bufH, b2, g2, be2, bufB);

    // ---- layer 3 ----
    gemm10_alpha<<<cdiv(NN * 32, TB), TB>>>(bufB, W3, a3s, a3d, bufA, als, ald);
    aggregate10_lsm<<<cdiv(NN * 32, 128), 128>>>(csr, rowptr, deg, als, ald, bufA, b3, out);
}

// round 14
// speedup vs baseline: 1.2283x; 1.0427x over previous
#include <cuda_runtime.h>
#include <cuda_fp16.h>
#include <math.h>
#include <stdint.h>

#define NN 100000
#define EE 1600000
#define ET (EE + NN)
#define F_IN 500
#define HID 16
#define HEADS 8
#define F1 (HEADS * HID)   // 128
#define NCLS 10

// ---------------- scratch (static device globals) ---------------------------
__device__ __half g_bufH[(size_t)NN * F1];   // fp16 features (gemm output)
__device__ __half g_bufH2[(size_t)NN * F1];  // fp16 layer-2 aggregate output
__device__ float  g_bufA[(size_t)NN * F1];   // fp32 (layer-3 gemm out)
__device__ float  g_bufB[(size_t)NN * F1];   // fp32 layer-1 aggregate output
__device__ float  g_als[(size_t)NN * HEADS];
__device__ float  g_ald[(size_t)NN * HEADS];
__device__ int    g_deg[NN];
__device__ int    g_rowptr[NN];
__device__ int    g_cursor[NN];
__device__ int    g_bsum[256];
__device__ int    g_boff[256];
__device__ int    g_csr[(size_t)ET];         // src node per CSR slot

static inline int cdiv(int a, int b) { return (a + b - 1) / b; }

__device__ __forceinline__ uint32_t smem_u32(const void* p) {
    uint32_t a;
    asm("{ .reg .u64 t; cvta.to.shared.u64 t, %1; cvt.u32.u64 %0, t; }"
        : "=r"(a) : "l"(p));
    return a;
}

// ---------------- tiny utils -------------------------------------------------
__global__ void fill_i(int* p, int v, int n) {
    int i = blockIdx.x * blockDim.x + threadIdx.x;
    if (i < n) p[i] = v;
}

// ---------------- CSR build --------------------------------------------------
__global__ void hist_dst(const int* __restrict__ ei, int* __restrict__ deg) {
    int e = blockIdx.x * blockDim.x + threadIdx.x;
    if (e >= ET) return;
    int dst = (e < EE) ? ei[EE + e] : (e - EE);
    atomicAdd(&deg[dst], 1);
}

#define SCAN_ELEMS 512
__global__ void scan_s1(const int* __restrict__ deg, int* __restrict__ bsum) {
    __shared__ int sm[256];
    int base = blockIdx.x * SCAN_ELEMS;
    int t = threadIdx.x;
    int i0 = base + 2 * t, i1 = base + 2 * t + 1;
    int v = 0;
    if (i0 < NN) v += deg[i0];
    if (i1 < NN) v += deg[i1];
    sm[t] = v;
    __syncthreads();
    for (int off = 128; off > 0; off >>= 1) {
        if (t < off) sm[t] += sm[t + off];
        __syncthreads();
    }
    if (t == 0) bsum[blockIdx.x] = sm[0];
}
__global__ void scan_s2(const int* __restrict__ bsum, int* __restrict__ boff, int nb) {
    __shared__ int sm[256];
    int t = threadIdx.x;
    int v = (t < nb) ? bsum[t] : 0;
    sm[t] = v;
    __syncthreads();
    for (int off = 1; off < 256; off <<= 1) {
        int add = (t >= off) ? sm[t - off] : 0;
        __syncthreads();
        sm[t] += add;
        __syncthreads();
    }
    if (t < nb) boff[t] = sm[t] - v;   // exclusive
}
__global__ void scan_s3(const int* __restrict__ deg, const int* __restrict__ boff,
                        int* __restrict__ rowptr, int* __restrict__ cursor) {
    __shared__ int sm[256];
    int base = blockIdx.x * SCAN_ELEMS;
    int t = threadIdx.x;
    int i0 = base + 2 * t, i1 = base + 2 * t + 1;
    int v0 = (i0 < NN) ? deg[i0] : 0;
    int v1 = (i1 < NN) ? deg[i1] : 0;
    int s = v0 + v1;
    sm[t] = s;
    __syncthreads();
    for (int off = 1; off < 256; off <<= 1) {
        int add = (t >= off) ? sm[t - off] : 0;
        __syncthreads();
        sm[t] += add;
        __syncthreads();
    }
    int ex = sm[t] - s + boff[blockIdx.x];
    if (i0 < NN) { rowptr[i0] = ex;      cursor[i0] = ex; }
    if (i1 < NN) { rowptr[i1] = ex + v0; cursor[i1] = ex + v0; }
}

__global__ void csr_scatter(const int* __restrict__ ei, int* __restrict__ cursor,
                            int* __restrict__ csr) {
    int e = blockIdx.x * blockDim.x + threadIdx.x;
    if (e >= ET) return;
    int src, dst;
    if (e < EE) { src = ei[e]; dst = ei[EE + e]; }
    else        { src = dst = e - EE; }
    int pos = atomicAdd(&cursor[dst], 1);
    csr[pos] = src;
}

// ======== tf32 mma.sync GEMM + fused alpha epilogue =========================
#define TM 128
#define KCH 16
#define ASTR 20
#define BSTR 136
#define ABYTES (TM * ASTR * 4)
#define BBYTES (KCH * BSTR * 4)
#define STAGEB (ABYTES + BBYTES)
#define NSTAGE 3
#define GSMEM (NSTAGE * STAGEB)

__global__ __launch_bounds__(128, 2) void gemm_tc(const float* __restrict__ A,
                                                  const float* __restrict__ B,
                                                  __half* __restrict__ H,
                                                  const float* __restrict__ a_src,
                                                  const float* __restrict__ a_dst,
                                                  float* __restrict__ als,
                                                  float* __restrict__ ald,
                                                  int M, int K) {
    extern __shared__ float smf[];
    __shared__ float s_as[F1], s_ad[F1];
    uint32_t sbase = smem_u32(smf);
    int tid = threadIdx.x, lane = tid & 31, wid = tid >> 5;
    int wm = (wid & 1) * 64, wn = (wid >> 1) * 64;
    int row0 = blockIdx.x * TM;
    int gid = lane >> 2, tk = lane & 3;
    int niter = (K + KCH - 1) / KCH;

    s_as[tid] = a_src[tid];
    s_ad[tid] = a_dst[tid];

    float acc[4][8][4];
#pragma unroll
    for (int mi = 0; mi < 4; mi++)
#pragma unroll
        for (int ni = 0; ni < 8; ni++)
#pragma unroll
            for (int q = 0; q < 4; q++) acc[mi][ni][q] = 0.f;

    auto load_stage = [&](int s, int k0) {
        uint32_t aB = sbase + s * STAGEB;
        uint32_t bB = aB + ABYTES;
#pragma unroll
        for (int i = 0; i < 4; i++) {
            int id = tid + i * 128;
            int r = id >> 2, c4 = id & 3;
            int gk = k0 + c4 * 4;
            const float* gp = A + (size_t)(row0 + r) * K + gk;
            int remain = K - gk;
            int bytes = 16;
            if (row0 + r >= M || remain <= 0) bytes = 0;
            else if (remain < 4) bytes = remain * 4;
            uint32_t dst = aB + (uint32_t)(r * ASTR + c4 * 4) * 4u;
            asm volatile("cp.async.ca.shared.global [%0], [%1], 16, %2;"
                         :: "r"(dst), "l"(gp), "r"(bytes));
        }
#pragma unroll
        for (int i = 0; i < 4; i++) {
            int id = tid + i * 128;
            int k = id >> 5, c4 = id & 31;
            const float* gp = B + (size_t)(k0 + k) * 128 + c4 * 4;
            int bytes = (k0 + k < K) ? 16 : 0;
            uint32_t dst = bB + (uint32_t)(k * BSTR + c4 * 4) * 4u;
            asm volatile("cp.async.ca.shared.global [%0], [%1], 16, %2;"
                         :: "r"(dst), "l"(gp), "r"(bytes));
        }
        asm volatile("cp.async.commit_group;");
    };

    load_stage(0, 0);
    if (niter > 1) load_stage(1, KCH);

    for (int it = 0; it < niter; it++) {
        if (it + 1 < niter) asm volatile("cp.async.wait_group 1;");
        else                asm volatile("cp.async.wait_group 0;");
        __syncthreads();
        if (it + 2 < niter) load_stage((it + 2) % NSTAGE, (it + 2) * KCH);

        const float* As = smf + ((it % NSTAGE) * STAGEB) / 4;
        const float* Bs = As + ABYTES / 4;
#pragma unroll
        for (int ks = 0; ks < 2; ks++) {
            int kb = ks * 8;
            uint32_t af[4][4];
#pragma unroll
            for (int mi = 0; mi < 4; mi++) {
                int r = wm + mi * 16 + gid;
                af[mi][0] = __float_as_uint(As[r * ASTR + kb + tk]);
                af[mi][1] = __float_as_uint(As[(r + 8) * ASTR + kb + tk]);
                af[mi][2] = __float_as_uint(As[r * ASTR + kb + tk + 4]);
                af[mi][3] = __float_as_uint(As[(r + 8) * ASTR + kb + tk + 4]);
            }
            uint32_t bf[8][2];
#pragma unroll
            for (int ni = 0; ni < 8; ni++) {
                int c = wn + ni * 8 + gid;
                bf[ni][0] = __float_as_uint(Bs[(kb + tk) * BSTR + c]);
                bf[ni][1] = __float_as_uint(Bs[(kb + tk + 4) * BSTR + c]);
            }
#pragma unroll
            for (int mi = 0; mi < 4; mi++)
#pragma unroll
                for (int ni = 0; ni < 8; ni++) {
                    asm volatile(
                        "mma.sync.aligned.m16n8k8.row.col.f32.tf32.tf32.f32 "
                        "{%0,%1,%2,%3}, {%4,%5,%6,%7}, {%8,%9}, {%0,%1,%2,%3};"
                        : "+f"(acc[mi][ni][0]), "+f"(acc[mi][ni][1]),
                          "+f"(acc[mi][ni][2]), "+f"(acc[mi][ni][3])
                        : "r"(af[mi][0]), "r"(af[mi][1]), "r"(af[mi][2]), "r"(af[mi][3]),
                          "r"(bf[ni][0]), "r"(bf[ni][1]));
                }
        }
        __syncthreads();
    }

    // ---- fused alpha epilogue ----
#pragma unroll
    for (int mi = 0; mi < 4; mi++) {
#pragma unroll
        for (int half = 0; half < 2; half++) {
            int row = row0 + wm + mi * 16 + half * 8 + gid;
#pragma unroll
            for (int hl = 0; hl < 4; hl++) {
                float ps = 0.f, pd = 0.f;
#pragma unroll
                for (int nj = 0; nj < 2; nj++) {
                    int ni = hl * 2 + nj;
                    int c0 = wn + ni * 8 + tk * 2;
                    float q0 = acc[mi][ni][half * 2 + 0];
                    float q1 = acc[mi][ni][half * 2 + 1];
                    ps += q0 * s_as[c0] + q1 * s_as[c0 + 1];
                    pd += q0 * s_ad[c0] + q1 * s_ad[c0 + 1];
                }
                ps += __shfl_xor_sync(0xffffffffu, ps, 1);
                ps += __shfl_xor_sync(0xffffffffu, ps, 2);
                pd += __shfl_xor_sync(0xffffffffu, pd, 1);
                pd += __shfl_xor_sync(0xffffffffu, pd, 2);
                if (tk == 0 && row < M) {
                    int h = (wn >> 4) + hl;
                    als[(size_t)row * HEADS + h] = ps;
                    ald[(size_t)row * HEADS + h] = pd;
                }
            }
        }
    }

    // ---- fp16 feature store ----
#pragma unroll
    for (int mi = 0; mi < 4; mi++) {
        int r0 = row0 + wm + mi * 16 + gid;
        int r1 = r0 + 8;
#pragma unroll
        for (int ni = 0; ni < 8; ni++) {
            int c = wn + ni * 8 + tk * 2;
            if (r0 < M)
                *(__half2*)(H + (size_t)r0 * 128 + c) =
                    __floats2half2_rn(acc[mi][ni][0], acc[mi][ni][1]);
            if (r1 < M)
                *(__half2*)(H + (size_t)r1 * 128 + c) =
                    __floats2half2_rn(acc[mi][ni][2], acc[mi][ni][3]);
        }
    }
}

// ---------------- fused aggregation (layers 1,2), unroll 4 -------------------
template <typename OUT>
__global__ __launch_bounds__(128) void aggregate_fused(
    const int* __restrict__ csr, const int* __restrict__ rowptr,
    const int* __restrict__ deg, const float* __restrict__ als,
    const float* __restrict__ ald, const __half* __restrict__ hfeat,
    const float* __restrict__ bias, const float* __restrict__ gamma,
    const float* __restrict__ beta, OUT* __restrict__ out) {
    __shared__ float4 s_acc[3][32];
    __shared__ float  s_d[4][8];
    int n = blockIdx.x;
    int t = threadIdx.x;
    int w = t >> 5, l = t & 31;
    int h = l >> 2;
    int c0 = l * 4;
    int start = rowptr[n];
    int len = deg[n];
    float myald = __ldg(&ald[(size_t)n * HEADS + h]);

    float4 acc = make_float4(0.f, 0.f, 0.f, 0.f);
    float dsum = 0.f;

    auto edge = [&](int s) {
        const __half2* hp = (const __half2*)(hfeat + (size_t)s * F1) + l * 2;
        __half2 q0 = __ldg(hp);
        __half2 q1 = __ldg(hp + 1);
        float al = __ldg(&als[(size_t)s * HEADS + h]) + myald;
        al = al > 0.f ? al : 0.2f * al;
        float p = __expf(al);
        dsum += p;
        float2 f0 = __half22float2(q0);
        float2 f1 = __half22float2(q1);
        acc.x = fmaf(p, f0.x, acc.x);
        acc.y = fmaf(p, f0.y, acc.y);
        acc.z = fmaf(p, f1.x, acc.z);
        acc.w = fmaf(p, f1.y, acc.w);
    };

    int i = w;
    for (; i + 12 < len; i += 16) {
        int s0 = __ldg(&csr[start + i]);
        int s1 = __ldg(&csr[start + i + 4]);
        int s2 = __ldg(&csr[start + i + 8]);
        int s3 = __ldg(&csr[start + i + 12]);
        edge(s0); edge(s1); edge(s2); edge(s3);
    }
    for (; i + 4 < len; i += 8) {
        int s0 = __ldg(&csr[start + i]);
        int s1 = __ldg(&csr[start + i + 4]);
        edge(s0); edge(s1);
    }
    if (i < len) {
        int s0 = __ldg(&csr[start + i]);
        edge(s0);
    }

    if (w > 0) s_acc[w - 1][l] = acc;
    if ((l & 3) == 0) s_d[w][h] = dsum;
    __syncthreads();
    if (w == 0) {
        float4 a1 = s_acc[0][l], a2 = s_acc[1][l], a3 = s_acc[2][l];
        acc.x += a1.x + a2.x + a3.x;
        acc.y += a1.y + a2.y + a3.y;
        acc.z += a1.z + a2.z + a3.z;
        acc.w += a1.w + a2.w + a3.w;
        float dall = s_d[0][h] + s_d[1][h] + s_d[2][h] + s_d[3][h];
        float invd = 1.f / fmaxf(dall, 1e-16f);
        float4 bb = *(const float4*)(bias + c0);
        float4 gg = *(const float4*)(gamma + c0);
        float4 be = *(const float4*)(beta + c0);
        float bnf = rsqrtf(1.0f + 1e-5f);
        float v0 = acc.x * invd + bb.x;
        float v1 = acc.y * invd + bb.y;
        float v2 = acc.z * invd + bb.z;
        float v3 = acc.w * invd + bb.w;
        v0 = v0 > 0.f ? v0 : (__expf(v0) - 1.f);
        v1 = v1 > 0.f ? v1 : (__expf(v1) - 1.f);
        v2 = v2 > 0.f ? v2 : (__expf(v2) - 1.f);
        v3 = v3 > 0.f ? v3 : (__expf(v3) - 1.f);
        float r0 = v0 * gg.x * bnf + be.x;
        float r1 = v1 * gg.y * bnf + be.y;
        float r2 = v2 * gg.z * bnf + be.z;
        float r3 = v3 * gg.w * bnf + be.w;
        if constexpr (sizeof(OUT) == 2) {
            __half2* op = (__half2*)((__half*)out + (size_t)n * F1 + c0);
            op[0] = __floats2half2_rn(r0, r1);
            op[1] = __floats2half2_rn(r2, r3);
        } else {
            *(float4*)((float*)out + (size_t)n * F1 + c0) = make_float4(r0, r1, r2, r3);
        }
    }
}

// ---------------- layer 3: fused GEMM(128->10) + node alphas (fp16 in) ------
__global__ void gemm10_alpha(const __half* __restrict__ A, const float* __restrict__ W,
                             const float* __restrict__ a3s, const float* __restrict__ a3d,
                             float* __restrict__ C, float* __restrict__ als,
                             float* __restrict__ ald) {
    __shared__ float Ws[F1 * NCLS];
    for (int i = threadIdx.x; i < F1 * NCLS; i += blockDim.x) Ws[i] = W[i];
    __syncthreads();
    int warp = (blockIdx.x * blockDim.x + threadIdx.x) >> 5;
    int lane = threadIdx.x & 31;
    if (warp >= NN) return;
    float acc[NCLS];
#pragma unroll
    for (int c = 0; c < NCLS; c++) acc[c] = 0.f;
    const __half2* arow = (const __half2*)(A + (size_t)warp * F1);
#pragma unroll
    for (int q = 0; q < 2; q++) {
        int k2 = lane + q * 32;           // half2 index: covers 64 pairs = 128 elems
        float2 av = __half22float2(__ldg(arow + k2));
        int k = k2 * 2;
#pragma unroll
        for (int c = 0; c < NCLS; c++)
            acc[c] += av.x * Ws[k * NCLS + c] + av.y * Ws[(k + 1) * NCLS + c];
    }
#pragma unroll
    for (int off = 16; off > 0; off >>= 1)
#pragma unroll
        for (int c = 0; c < NCLS; c++) acc[c] += __shfl_xor_sync(0xffffffffu, acc[c], off);
    if (lane < NCLS) C[(size_t)warp * NCLS + lane] = acc[lane];
    if (lane == 0) {
        float s = 0.f, d = 0.f;
#pragma unroll
        for (int c = 0; c < NCLS; c++) {
            s += acc[c] * __ldg(&a3s[c]);
            d += acc[c] * __ldg(&a3d[c]);
        }
        als[warp] = s;
        ald[warp] = d;
    }
}

// ---------------- layer 3: fused aggregation + bias + log_softmax ------------
__global__ __launch_bounds__(128) void aggregate10_lsm(
    const int* __restrict__ csr, const int* __restrict__ rowptr,
    const int* __restrict__ deg, const float* __restrict__ als,
    const float* __restrict__ ald, const float* __restrict__ hfeat,
    const float* __restrict__ b3, float* __restrict__ out) {
    int warp = (blockIdx.x * blockDim.x + threadIdx.x) >> 5;
    int lane = threadIdx.x & 31;
    if (warp >= NN) return;
    int n = warp;
    int start = rowptr[n];
    int len = deg[n];
    float myald = (lane == 0) ? __ldg(&ald[n]) : 0.f;
    float acc = 0.f, dsum = 0.f;
    int i = 0;
    for (; i + 2 <= len; i += 2) {
        int s0 = __ldg(&csr[start + i]);
        int s1 = __ldg(&csr[start + i + 1]);
        float f0 = (lane < NCLS) ? __ldg(&hfeat[(size_t)s0 * NCLS + lane]) : 0.f;
        float f1 = (lane < NCLS) ? __ldg(&hfeat[(size_t)s1 * NCLS + lane]) : 0.f;
        float p0 = 0.f, p1 = 0.f;
        if (lane == 0) {
            float l0 = __ldg(&als[s0]) + myald;
            float l1 = __ldg(&als[s1]) + myald;
            l0 = l0 > 0.f ? l0 : 0.2f * l0;
            l1 = l1 > 0.f ? l1 : 0.2f * l1;
            p0 = __expf(l0);
            p1 = __expf(l1);
        }
        p0 = __shfl_sync(0xffffffffu, p0, 0);
        p1 = __shfl_sync(0xffffffffu, p1, 0);
        dsum += p0 + p1;
        acc = fmaf(p0, f0, fmaf(p1, f1, acc));
    }
    if (i < len) {
        int s0 = __ldg(&csr[start + i]);
        float f0 = (lane < NCLS) ? __ldg(&hfeat[(size_t)s0 * NCLS + lane]) : 0.f;
        float p0 = 0.f;
        if (lane == 0) {
            float l0 = __ldg(&als[s0]) + myald;
            l0 = l0 > 0.f ? l0 : 0.2f * l0;
            p0 = __expf(l0);
        }
        p0 = __shfl_sync(0xffffffffu, p0, 0);
        dsum += p0;
        acc = fmaf(p0, f0, acc);
    }
    float invd = 1.f / fmaxf(dsum, 1e-16f);
    float val = (lane < NCLS) ? acc * invd + __ldg(&b3[lane]) : -1e30f;
    float m = val;
#pragma unroll
    for (int off = 16; off > 0; off >>= 1)
        m = fmaxf(m, __shfl_xor_sync(0xffffffffu, m, off));
    float ex = (lane < NCLS) ? expf(val - m) : 0.f;
    float ssum = ex;
#pragma unroll
    for (int off = 16; off > 0; off >>= 1)
        ssum += __shfl_xor_sync(0xffffffffu, ssum, off);
    float l = m + logf(ssum);
    if (lane < NCLS) out[(size_t)n * NCLS + lane] = val - l;
}

// ---------------- driver -----------------------------------------------------
extern "C" void kernel_launch(void* const* d_in, const int* in_sizes, int n_in,
                              void* d_out, int out_size) {
    const float* x    = (const float*)d_in[0];
    const int*   ei   = (const int*)d_in[1];
    const float* W1   = (const float*)d_in[2];
    const float* a1s  = (const float*)d_in[3];
    const float* a1d  = (const float*)d_in[4];
    const float* b1   = (const float*)d_in[5];
    const float* g1   = (const float*)d_in[6];
    const float* be1  = (const float*)d_in[7];
    const float* W2   = (const float*)d_in[8];
    const float* a2s  = (const float*)d_in[9];
    const float* a2d  = (const float*)d_in[10];
    const float* b2   = (const float*)d_in[11];
    const float* g2   = (const float*)d_in[12];
    const float* be2  = (const float*)d_in[13];
    const float* W3   = (const float*)d_in[14];
    const float* a3s  = (const float*)d_in[15];
    const float* a3d  = (const float*)d_in[16];
    const float* b3   = (const float*)d_in[17];
    float* out = (float*)d_out;

    __half *bufH, *bufH2;
    float *bufA, *bufB, *als, *ald;
    int *deg, *rowptr, *cursor, *bsum, *boff, *csr;
    cudaGetSymbolAddress((void**)&bufH, g_bufH);
    cudaGetSymbolAddress((void**)&bufH2, g_bufH2);
    cudaGetSymbolAddress((void**)&bufA, g_bufA);
    cudaGetSymbolAddress((void**)&bufB, g_bufB);
    cudaGetSymbolAddress((void**)&als, g_als);
    cudaGetSymbolAddress((void**)&ald, g_ald);
    cudaGetSymbolAddress((void**)&deg, g_deg);
    cudaGetSymbolAddress((void**)&rowptr, g_rowptr);
    cudaGetSymbolAddress((void**)&cursor, g_cursor);
    cudaGetSymbolAddress((void**)&bsum, g_bsum);
    cudaGetSymbolAddress((void**)&boff, g_boff);
    cudaGetSymbolAddress((void**)&csr, g_csr);

    cudaFuncSetAttribute(gemm_tc, cudaFuncAttributeMaxDynamicSharedMemorySize, GSMEM);

    static cudaStream_t s2 = nullptr;
    static cudaEvent_t evFork = nullptr, evJoin = nullptr;
    if (s2 == nullptr) {
        cudaStreamCreate(&s2);
        cudaEventCreateWithFlags(&evFork, cudaEventDisableTiming);
        cudaEventCreateWithFlags(&evJoin, cudaEventDisableTiming);
    }

    const int TB = 256;
    const int NB_SCAN = cdiv(NN, SCAN_ELEMS);
    const int NGRID = cdiv(NN, TM);

    // ---- fork: CSR build on s2, GEMM1 on main stream ----
    cudaEventRecord(evFork, 0);
    cudaStreamWaitEvent(s2, evFork, 0);

    fill_i<<<cdiv(NN, TB), TB, 0, s2>>>(deg, 0, NN);
    hist_dst<<<cdiv(ET, TB), TB, 0, s2>>>(ei, deg);
    scan_s1<<<NB_SCAN, 256, 0, s2>>>(deg, bsum);
    scan_s2<<<1, 256, 0, s2>>>(bsum, boff, NB_SCAN);
    scan_s3<<<NB_SCAN, 256, 0, s2>>>(deg, boff, rowptr, cursor);
    csr_scatter<<<cdiv(ET, TB), TB, 0, s2>>>(ei, cursor, csr);
    cudaEventRecord(evJoin, s2);

    gemm_tc<<<NGRID, 128, GSMEM>>>(x, W1, bufH, a1s, a1d, als, ald, NN, F_IN);

    cudaStreamWaitEvent(0, evJoin, 0);

    // ---- layer 1 aggregation (fp32 out -> GEMM2 input) ----
    aggregate_fused<float><<<NN, 128>>>(csr, rowptr, deg, als, ald, bufH,
                                        b1, g1, be1, bufB);

    // ---- layer 2 ----
    gemm_tc<<<NGRID, 128, GSMEM>>>(bufB, W2, bufH, a2s, a2d, als, ald, NN, F1);
    aggregate_fused<__half><<<NN, 128>>>(csr, rowptr, deg, als, ald, bufH,
                                         b2, g2, be2, bufH2);

    // ---- layer 3 ----
    gemm10_alpha<<<cdiv(NN * 32, TB), TB>>>(bufH2, W3, a3s, a3d, bufA, als, ald);
    aggregate10_lsm<<<cdiv(NN * 32, 128), 128>>>(csr, rowptr, deg, als, ald, bufA, b3, out);
}

// round 15
// speedup vs baseline: 1.3235x; 1.0775x over previous
#include <cuda_runtime.h>
#include <cuda_fp16.h>
#include <math.h>
#include <stdint.h>

#define NN 100000
#define EE 1600000
#define ET (EE + NN)
#define F_IN 500
#define HID 16
#define HEADS 8
#define F1 (HEADS * HID)   // 128
#define NCLS 10

// ---------------- scratch (static device globals) ---------------------------
__device__ __half g_bufH[(size_t)NN * F1];   // fp16 features (gemm output)
__device__ __half g_bufH2[(size_t)NN * F1];  // fp16 layer-2 aggregate output
__device__ float  g_bufA[(size_t)NN * F1];   // fp32 (layer-3 gemm out)
__device__ float  g_bufB[(size_t)NN * F1];   // fp32 layer-1 aggregate output
__device__ float  g_als[(size_t)NN * HEADS];
__device__ float  g_ald[(size_t)NN * HEADS];
__device__ int    g_deg[NN];
__device__ int    g_rowptr[NN];
__device__ int    g_cursor[NN];
__device__ int    g_bsum[256];
__device__ int    g_boff[256];
__device__ int    g_csr[(size_t)ET];         // src node per CSR slot

static inline int cdiv(int a, int b) { return (a + b - 1) / b; }

__device__ __forceinline__ uint32_t smem_u32(const void* p) {
    uint32_t a;
    asm("{ .reg .u64 t; cvta.to.shared.u64 t, %1; cvt.u32.u64 %0, t; }"
        : "=r"(a) : "l"(p));
    return a;
}

// ---------------- tiny utils -------------------------------------------------
__global__ void fill_i(int* p, int v, int n) {
    int i = blockIdx.x * blockDim.x + threadIdx.x;
    if (i < n) p[i] = v;
}

// ---------------- CSR build --------------------------------------------------
__global__ void hist_dst(const int* __restrict__ ei, int* __restrict__ deg) {
    int e = blockIdx.x * blockDim.x + threadIdx.x;
    if (e >= ET) return;
    int dst = (e < EE) ? ei[EE + e] : (e - EE);
    atomicAdd(&deg[dst], 1);
}

#define SCAN_ELEMS 512
__global__ void scan_s1(const int* __restrict__ deg, int* __restrict__ bsum) {
    __shared__ int sm[256];
    int base = blockIdx.x * SCAN_ELEMS;
    int t = threadIdx.x;
    int i0 = base + 2 * t, i1 = base + 2 * t + 1;
    int v = 0;
    if (i0 < NN) v += deg[i0];
    if (i1 < NN) v += deg[i1];
    sm[t] = v;
    __syncthreads();
    for (int off = 128; off > 0; off >>= 1) {
        if (t < off) sm[t] += sm[t + off];
        __syncthreads();
    }
    if (t == 0) bsum[blockIdx.x] = sm[0];
}
__global__ void scan_s2(const int* __restrict__ bsum, int* __restrict__ boff, int nb) {
    __shared__ int sm[256];
    int t = threadIdx.x;
    int v = (t < nb) ? bsum[t] : 0;
    sm[t] = v;
    __syncthreads();
    for (int off = 1; off < 256; off <<= 1) {
        int add = (t >= off) ? sm[t - off] : 0;
        __syncthreads();
        sm[t] += add;
        __syncthreads();
    }
    if (t < nb) boff[t] = sm[t] - v;   // exclusive
}
__global__ void scan_s3(const int* __restrict__ deg, const int* __restrict__ boff,
                        int* __restrict__ rowptr, int* __restrict__ cursor) {
    __shared__ int sm[256];
    int base = blockIdx.x * SCAN_ELEMS;
    int t = threadIdx.x;
    int i0 = base + 2 * t, i1 = base + 2 * t + 1;
    int v0 = (i0 < NN) ? deg[i0] : 0;
    int v1 = (i1 < NN) ? deg[i1] : 0;
    int s = v0 + v1;
    sm[t] = s;
    __syncthreads();
    for (int off = 1; off < 256; off <<= 1) {
        int add = (t >= off) ? sm[t - off] : 0;
        __syncthreads();
        sm[t] += add;
        __syncthreads();
    }
    int ex = sm[t] - s + boff[blockIdx.x];
    if (i0 < NN) { rowptr[i0] = ex;      cursor[i0] = ex; }
    if (i1 < NN) { rowptr[i1] = ex + v0; cursor[i1] = ex + v0; }
}

__global__ void csr_scatter(const int* __restrict__ ei, int* __restrict__ cursor,
                            int* __restrict__ csr) {
    int e = blockIdx.x * blockDim.x + threadIdx.x;
    if (e >= ET) return;
    int src, dst;
    if (e < EE) { src = ei[e]; dst = ei[EE + e]; }
    else        { src = dst = e - EE; }
    int pos = atomicAdd(&cursor[dst], 1);
    csr[pos] = src;
}

// ======== tf32 mma.sync GEMM + fused alpha epilogue =========================
#define TM 128
#define KCH 16
#define ASTR 20
#define BSTR 136
#define ABYTES (TM * ASTR * 4)
#define BBYTES (KCH * BSTR * 4)
#define STAGEB (ABYTES + BBYTES)
#define NSTAGE 3
#define GSMEM (NSTAGE * STAGEB)

__global__ __launch_bounds__(128, 2) void gemm_tc(const float* __restrict__ A,
                                                  const float* __restrict__ B,
                                                  __half* __restrict__ H,
                                                  const float* __restrict__ a_src,
                                                  const float* __restrict__ a_dst,
                                                  float* __restrict__ als,
                                                  float* __restrict__ ald,
                                                  int M, int K) {
    extern __shared__ float smf[];
    __shared__ float s_as[F1], s_ad[F1];
    uint32_t sbase = smem_u32(smf);
    int tid = threadIdx.x, lane = tid & 31, wid = tid >> 5;
    int wm = (wid & 1) * 64, wn = (wid >> 1) * 64;
    int row0 = blockIdx.x * TM;
    int gid = lane >> 2, tk = lane & 3;
    int niter = (K + KCH - 1) / KCH;

    s_as[tid] = a_src[tid];
    s_ad[tid] = a_dst[tid];

    float acc[4][8][4];
#pragma unroll
    for (int mi = 0; mi < 4; mi++)
#pragma unroll
        for (int ni = 0; ni < 8; ni++)
#pragma unroll
            for (int q = 0; q < 4; q++) acc[mi][ni][q] = 0.f;

    auto load_stage = [&](int s, int k0) {
        uint32_t aB = sbase + s * STAGEB;
        uint32_t bB = aB + ABYTES;
#pragma unroll
        for (int i = 0; i < 4; i++) {
            int id = tid + i * 128;
            int r = id >> 2, c4 = id & 3;
            int gk = k0 + c4 * 4;
            const float* gp = A + (size_t)(row0 + r) * K + gk;
            int remain = K - gk;
            int bytes = 16;
            if (row0 + r >= M || remain <= 0) bytes = 0;
            else if (remain < 4) bytes = remain * 4;
            uint32_t dst = aB + (uint32_t)(r * ASTR + c4 * 4) * 4u;
            asm volatile("cp.async.ca.shared.global [%0], [%1], 16, %2;"
                         :: "r"(dst), "l"(gp), "r"(bytes));
        }
#pragma unroll
        for (int i = 0; i < 4; i++) {
            int id = tid + i * 128;
            int k = id >> 5, c4 = id & 31;
            const float* gp = B + (size_t)(k0 + k) * 128 + c4 * 4;
            int bytes = (k0 + k < K) ? 16 : 0;
            uint32_t dst = bB + (uint32_t)(k * BSTR + c4 * 4) * 4u;
            asm volatile("cp.async.ca.shared.global [%0], [%1], 16, %2;"
                         :: "r"(dst), "l"(gp), "r"(bytes));
        }
        asm volatile("cp.async.commit_group;");
    };

    load_stage(0, 0);
    if (niter > 1) load_stage(1, KCH);

    for (int it = 0; it < niter; it++) {
        if (it + 1 < niter) asm volatile("cp.async.wait_group 1;");
        else                asm volatile("cp.async.wait_group 0;");
        __syncthreads();
        if (it + 2 < niter) load_stage((it + 2) % NSTAGE, (it + 2) * KCH);

        const float* As = smf + ((it % NSTAGE) * STAGEB) / 4;
        const float* Bs = As + ABYTES / 4;
#pragma unroll
        for (int ks = 0; ks < 2; ks++) {
            int kb = ks * 8;
            uint32_t af[4][4];
#pragma unroll
            for (int mi = 0; mi < 4; mi++) {
                int r = wm + mi * 16 + gid;
                af[mi][0] = __float_as_uint(As[r * ASTR + kb + tk]);
                af[mi][1] = __float_as_uint(As[(r + 8) * ASTR + kb + tk]);
                af[mi][2] = __float_as_uint(As[r * ASTR + kb + tk + 4]);
                af[mi][3] = __float_as_uint(As[(r + 8) * ASTR + kb + tk + 4]);
            }
            uint32_t bf[8][2];
#pragma unroll
            for (int ni = 0; ni < 8; ni++) {
                int c = wn + ni * 8 + gid;
                bf[ni][0] = __float_as_uint(Bs[(kb + tk) * BSTR + c]);
                bf[ni][1] = __float_as_uint(Bs[(kb + tk + 4) * BSTR + c]);
            }
#pragma unroll
            for (int mi = 0; mi < 4; mi++)
#pragma unroll
                for (int ni = 0; ni < 8; ni++) {
                    asm volatile(
                        "mma.sync.aligned.m16n8k8.row.col.f32.tf32.tf32.f32 "
                        "{%0,%1,%2,%3}, {%4,%5,%6,%7}, {%8,%9}, {%0,%1,%2,%3};"
                        : "+f"(acc[mi][ni][0]), "+f"(acc[mi][ni][1]),
                          "+f"(acc[mi][ni][2]), "+f"(acc[mi][ni][3])
                        : "r"(af[mi][0]), "r"(af[mi][1]), "r"(af[mi][2]), "r"(af[mi][3]),
                          "r"(bf[ni][0]), "r"(bf[ni][1]));
                }
        }
        __syncthreads();
    }

    // ---- fused alpha epilogue ----
#pragma unroll
    for (int mi = 0; mi < 4; mi++) {
#pragma unroll
        for (int half = 0; half < 2; half++) {
            int row = row0 + wm + mi * 16 + half * 8 + gid;
#pragma unroll
            for (int hl = 0; hl < 4; hl++) {
                float ps = 0.f, pd = 0.f;
#pragma unroll
                for (int nj = 0; nj < 2; nj++) {
                    int ni = hl * 2 + nj;
                    int c0 = wn + ni * 8 + tk * 2;
                    float q0 = acc[mi][ni][half * 2 + 0];
                    float q1 = acc[mi][ni][half * 2 + 1];
                    ps += q0 * s_as[c0] + q1 * s_as[c0 + 1];
                    pd += q0 * s_ad[c0] + q1 * s_ad[c0 + 1];
                }
                ps += __shfl_xor_sync(0xffffffffu, ps, 1);
                ps += __shfl_xor_sync(0xffffffffu, ps, 2);
                pd += __shfl_xor_sync(0xffffffffu, pd, 1);
                pd += __shfl_xor_sync(0xffffffffu, pd, 2);
                if (tk == 0 && row < M) {
                    int h = (wn >> 4) + hl;
                    als[(size_t)row * HEADS + h] = ps;
                    ald[(size_t)row * HEADS + h] = pd;
                }
            }
        }
    }

    // ---- fp16 feature store ----
#pragma unroll
    for (int mi = 0; mi < 4; mi++) {
        int r0 = row0 + wm + mi * 16 + gid;
        int r1 = r0 + 8;
#pragma unroll
        for (int ni = 0; ni < 8; ni++) {
            int c = wn + ni * 8 + tk * 2;
            if (r0 < M)
                *(__half2*)(H + (size_t)r0 * 128 + c) =
                    __floats2half2_rn(acc[mi][ni][0], acc[mi][ni][1]);
            if (r1 < M)
                *(__half2*)(H + (size_t)r1 * 128 + c) =
                    __floats2half2_rn(acc[mi][ni][2], acc[mi][ni][3]);
        }
    }
}

// ---------------- warp-per-node aggregation (layers 1,2) ---------------------
template <typename OUT>
__global__ __launch_bounds__(256) void aggregate_warp(
    const int* __restrict__ csr, const int* __restrict__ rowptr,
    const int* __restrict__ deg, const float* __restrict__ als,
    const float* __restrict__ ald, const __half* __restrict__ hfeat,
    const float* __restrict__ bias, const float* __restrict__ gamma,
    const float* __restrict__ beta, OUT* __restrict__ out) {
    int warp = (blockIdx.x * blockDim.x + threadIdx.x) >> 5;
    int l = threadIdx.x & 31;
    if (warp >= NN) return;
    int n = warp;
    int h = l >> 2;
    int c0 = l * 4;
    int start = rowptr[n];
    int len = deg[n];
    bool leader = (l & 3) == 0;
    int gsrc = l & ~3;              // broadcast source lane for my 4-lane group
    float myald = leader ? __ldg(&ald[(size_t)n * HEADS + h]) : 0.f;

    float4 acc = make_float4(0.f, 0.f, 0.f, 0.f);
    float dsum = 0.f;

    auto edge = [&](int s) {
        const __half2* hp = (const __half2*)(hfeat + (size_t)s * F1) + l * 2;
        __half2 q0 = __ldg(hp);
        __half2 q1 = __ldg(hp + 1);
        float p = 0.f;
        if (leader) {
            float al = __ldg(&als[(size_t)s * HEADS + h]) + myald;
            al = al > 0.f ? al : 0.2f * al;
            p = __expf(al);
        }
        p = __shfl_sync(0xffffffffu, p, gsrc);
        dsum += p;
        float2 f0 = __half22float2(q0);
        float2 f1 = __half22float2(q1);
        acc.x = fmaf(p, f0.x, acc.x);
        acc.y = fmaf(p, f0.y, acc.y);
        acc.z = fmaf(p, f1.x, acc.z);
        acc.w = fmaf(p, f1.y, acc.w);
    };

    int i = 0;
    for (; i + 4 <= len; i += 4) {
        int s0 = __ldg(&csr[start + i]);
        int s1 = __ldg(&csr[start + i + 1]);
        int s2 = __ldg(&csr[start + i + 2]);
        int s3 = __ldg(&csr[start + i + 3]);
        edge(s0); edge(s1); edge(s2); edge(s3);
    }
    for (; i < len; i++) {
        int s0 = __ldg(&csr[start + i]);
        edge(s0);
    }

    float invd = 1.f / fmaxf(dsum, 1e-16f);
    float4 bb = *(const float4*)(bias + c0);
    float4 gg = *(const float4*)(gamma + c0);
    float4 be = *(const float4*)(beta + c0);
    float bnf = rsqrtf(1.0f + 1e-5f);
    float v0 = acc.x * invd + bb.x;
    float v1 = acc.y * invd + bb.y;
    float v2 = acc.z * invd + bb.z;
    float v3 = acc.w * invd + bb.w;
    v0 = v0 > 0.f ? v0 : (__expf(v0) - 1.f);
    v1 = v1 > 0.f ? v1 : (__expf(v1) - 1.f);
    v2 = v2 > 0.f ? v2 : (__expf(v2) - 1.f);
    v3 = v3 > 0.f ? v3 : (__expf(v3) - 1.f);
    float r0 = v0 * gg.x * bnf + be.x;
    float r1 = v1 * gg.y * bnf + be.y;
    float r2 = v2 * gg.z * bnf + be.z;
    float r3 = v3 * gg.w * bnf + be.w;
    if constexpr (sizeof(OUT) == 2) {
        __half2* op = (__half2*)((__half*)out + (size_t)n * F1 + c0);
        op[0] = __floats2half2_rn(r0, r1);
        op[1] = __floats2half2_rn(r2, r3);
    } else {
        *(float4*)((float*)out + (size_t)n * F1 + c0) = make_float4(r0, r1, r2, r3);
    }
}

// ---------------- layer 3: fused GEMM(128->10) + node alphas (fp16 in) ------
__global__ void gemm10_alpha(const __half* __restrict__ A, const float* __restrict__ W,
                             const float* __restrict__ a3s, const float* __restrict__ a3d,
                             float* __restrict__ C, float* __restrict__ als,
                             float* __restrict__ ald) {
    __shared__ float Ws[F1 * NCLS];
    for (int i = threadIdx.x; i < F1 * NCLS; i += blockDim.x) Ws[i] = W[i];
    __syncthreads();
    int warp = (blockIdx.x * blockDim.x + threadIdx.x) >> 5;
    int lane = threadIdx.x & 31;
    if (warp >= NN) return;
    float acc[NCLS];
#pragma unroll
    for (int c = 0; c < NCLS; c++) acc[c] = 0.f;
    const __half2* arow = (const __half2*)(A + (size_t)warp * F1);
#pragma unroll
    for (int q = 0; q < 2; q++) {
        int k2 = lane + q * 32;
        float2 av = __half22float2(__ldg(arow + k2));
        int k = k2 * 2;
#pragma unroll
        for (int c = 0; c < NCLS; c++)
            acc[c] += av.x * Ws[k * NCLS + c] + av.y * Ws[(k + 1) * NCLS + c];
    }
#pragma unroll
    for (int off = 16; off > 0; off >>= 1)
#pragma unroll
        for (int c = 0; c < NCLS; c++) acc[c] += __shfl_xor_sync(0xffffffffu, acc[c], off);
    if (lane < NCLS) C[(size_t)warp * NCLS + lane] = acc[lane];
    if (lane == 0) {
        float s = 0.f, d = 0.f;
#pragma unroll
        for (int c = 0; c < NCLS; c++) {
            s += acc[c] * __ldg(&a3s[c]);
            d += acc[c] * __ldg(&a3d[c]);
        }
        als[warp] = s;
        ald[warp] = d;
    }
}

// ---------------- layer 3: fused aggregation + bias + log_softmax ------------
__global__ __launch_bounds__(128) void aggregate10_lsm(
    const int* __restrict__ csr, const int* __restrict__ rowptr,
    const int* __restrict__ deg, const float* __restrict__ als,
    const float* __restrict__ ald, const float* __restrict__ hfeat,
    const float* __restrict__ b3, float* __restrict__ out) {
    int warp = (blockIdx.x * blockDim.x + threadIdx.x) >> 5;
    int lane = threadIdx.x & 31;
    if (warp >= NN) return;
    int n = warp;
    int start = rowptr[n];
    int len = deg[n];
    float myald = (lane == 0) ? __ldg(&ald[n]) : 0.f;
    float acc = 0.f, dsum = 0.f;
    int i = 0;
    for (; i + 2 <= len; i += 2) {
        int s0 = __ldg(&csr[start + i]);
        int s1 = __ldg(&csr[start + i + 1]);
        float f0 = (lane < NCLS) ? __ldg(&hfeat[(size_t)s0 * NCLS + lane]) : 0.f;
        float f1 = (lane < NCLS) ? __ldg(&hfeat[(size_t)s1 * NCLS + lane]) : 0.f;
        float p0 = 0.f, p1 = 0.f;
        if (lane == 0) {
            float l0 = __ldg(&als[s0]) + myald;
            float l1 = __ldg(&als[s1]) + myald;
            l0 = l0 > 0.f ? l0 : 0.2f * l0;
            l1 = l1 > 0.f ? l1 : 0.2f * l1;
            p0 = __expf(l0);
            p1 = __expf(l1);
        }
        p0 = __shfl_sync(0xffffffffu, p0, 0);
        p1 = __shfl_sync(0xffffffffu, p1, 0);
        dsum += p0 + p1;
        acc = fmaf(p0, f0, fmaf(p1, f1, acc));
    }
    if (i < len) {
        int s0 = __ldg(&csr[start + i]);
        float f0 = (lane < NCLS) ? __ldg(&hfeat[(size_t)s0 * NCLS + lane]) : 0.f;
        float p0 = 0.f;
        if (lane == 0) {
            float l0 = __ldg(&als[s0]) + myald;
            l0 = l0 > 0.f ? l0 : 0.2f * l0;
            p0 = __expf(l0);
        }
        p0 = __shfl_sync(0xffffffffu, p0, 0);
        dsum += p0;
        acc = fmaf(p0, f0, acc);
    }
    float invd = 1.f / fmaxf(dsum, 1e-16f);
    float val = (lane < NCLS) ? acc * invd + __ldg(&b3[lane]) : -1e30f;
    float m = val;
#pragma unroll
    for (int off = 16; off > 0; off >>= 1)
        m = fmaxf(m, __shfl_xor_sync(0xffffffffu, m, off));
    float ex = (lane < NCLS) ? expf(val - m) : 0.f;
    float ssum = ex;
#pragma unroll
    for (int off = 16; off > 0; off >>= 1)
        ssum += __shfl_xor_sync(0xffffffffu, ssum, off);
    float l = m + logf(ssum);
    if (lane < NCLS) out[(size_t)n * NCLS + lane] = val - l;
}

// ---------------- driver -----------------------------------------------------
extern "C" void kernel_launch(void* const* d_in, const int* in_sizes, int n_in,
                              void* d_out, int out_size) {
    const float* x    = (const float*)d_in[0];
    const int*   ei   = (const int*)d_in[1];
    const float* W1   = (const float*)d_in[2];
    const float* a1s  = (const float*)d_in[3];
    const float* a1d  = (const float*)d_in[4];
    const float* b1   = (const float*)d_in[5];
    const float* g1   = (const float*)d_in[6];
    const float* be1  = (const float*)d_in[7];
    const float* W2   = (const float*)d_in[8];
    const float* a2s  = (const float*)d_in[9];
    const float* a2d  = (const float*)d_in[10];
    const float* b2   = (const float*)d_in[11];
    const float* g2   = (const float*)d_in[12];
    const float* be2  = (const float*)d_in[13];
    const float* W3   = (const float*)d_in[14];
    const float* a3s  = (const float*)d_in[15];
    const float* a3d  = (const float*)d_in[16];
    const float* b3   = (const float*)d_in[17];
    float* out = (float*)d_out;

    __half *bufH, *bufH2;
    float *bufA, *bufB, *als, *ald;
    int *deg, *rowptr, *cursor, *bsum, *boff, *csr;
    cudaGetSymbolAddress((void**)&bufH, g_bufH);
    cudaGetSymbolAddress((void**)&bufH2, g_bufH2);
    cudaGetSymbolAddress((void**)&bufA, g_bufA);
    cudaGetSymbolAddress((void**)&bufB, g_bufB);
    cudaGetSymbolAddress((void**)&als, g_als);
    cudaGetSymbolAddress((void**)&ald, g_ald);
    cudaGetSymbolAddress((void**)&deg, g_deg);
    cudaGetSymbolAddress((void**)&rowptr, g_rowptr);
    cudaGetSymbolAddress((void**)&cursor, g_cursor);
    cudaGetSymbolAddress((void**)&bsum, g_bsum);
    cudaGetSymbolAddress((void**)&boff, g_boff);
    cudaGetSymbolAddress((void**)&csr, g_csr);

    cudaFuncSetAttribute(gemm_tc, cudaFuncAttributeMaxDynamicSharedMemorySize, GSMEM);

    static cudaStream_t s2 = nullptr;
    static cudaEvent_t evFork = nullptr, evJoin = nullptr;
    if (s2 == nullptr) {
        cudaStreamCreate(&s2);
        cudaEventCreateWithFlags(&evFork, cudaEventDisableTiming);
        cudaEventCreateWithFlags(&evJoin, cudaEventDisableTiming);
    }

    const int TB = 256;
    const int NB_SCAN = cdiv(NN, SCAN_ELEMS);
    const int NGRID = cdiv(NN, TM);
    const int AGRID = cdiv(NN * 32, TB);

    // ---- fork: CSR build on s2, GEMM1 on main stream ----
    cudaEventRecord(evFork, 0);
    cudaStreamWaitEvent(s2, evFork, 0);

    fill_i<<<cdiv(NN, TB), TB, 0, s2>>>(deg, 0, NN);
    hist_dst<<<cdiv(ET, TB), TB, 0, s2>>>(ei, deg);
    scan_s1<<<NB_SCAN, 256, 0, s2>>>(deg, bsum);
    scan_s2<<<1, 256, 0, s2>>>(bsum, boff, NB_SCAN);
    scan_s3<<<NB_SCAN, 256, 0, s2>>>(deg, boff, rowptr, cursor);
    csr_scatter<<<cdiv(ET, TB), TB, 0, s2>>>(ei, cursor, csr);
    cudaEventRecord(evJoin, s2);

    gemm_tc<<<NGRID, 128, GSMEM>>>(x, W1, bufH, a1s, a1d, als, ald, NN, F_IN);

    cudaStreamWaitEvent(0, evJoin, 0);

    // ---- layer 1 aggregation (fp32 out -> GEMM2 input) ----
    aggregate_warp<float><<<AGRID, TB>>>(csr, rowptr, deg, als, ald, bufH,
                                         b1, g1, be1, bufB);

    // ---- layer 2 ----
    gemm_tc<<<NGRID, 128, GSMEM>>>(bufB, W2, bufH, a2s, a2d, als, ald, NN, F1);
    aggregate_warp<__half><<<AGRID, TB>>>(csr, rowptr, deg, als, ald, bufH,
                                          b2, g2, be2, bufH2);

    // ---- layer 3 ----
    gemm10_alpha<<<AGRID, TB>>>(bufH2, W3, a3s, a3d, bufA, als, ald);
    aggregate10_lsm<<<cdiv(NN * 32, 128), 128>>>(csr, rowptr, deg, als, ald, bufA, b3, out);
}

// round 17
// speedup vs baseline: 1.3402x; 1.0126x over previous
#include <cuda_runtime.h>
#include <cuda_fp16.h>
#include <math.h>
#include <stdint.h>

#define NN 100000
#define EE 1600000
#define ET (EE + NN)
#define F_IN 500
#define HID 16
#define HEADS 8
#define F1 (HEADS * HID)   // 128
#define NCLS 10

// ---------------- scratch (static device globals) ---------------------------
__device__ __half g_bufH[(size_t)NN * F1];   // fp16 features (gemm output / L3 logits)
__device__ __half g_bufH2[(size_t)NN * F1];  // fp16 layer-2 aggregate output
__device__ float  g_bufB[(size_t)NN * F1];   // fp32 layer-1 aggregate output
__device__ float  g_als[(size_t)NN * HEADS];
__device__ float  g_ald[(size_t)NN * HEADS];
__device__ int    g_deg[NN];
__device__ int    g_rowptr[NN];
__device__ int    g_cursor[NN];
__device__ int    g_bsum[256];
__device__ int    g_boff[256];
__device__ int    g_csr[(size_t)ET];         // src node per CSR slot

static inline int cdiv(int a, int b) { return (a + b - 1) / b; }

__device__ __forceinline__ uint32_t smem_u32(const void* p) {
    uint32_t a;
    asm("{ .reg .u64 t; cvta.to.shared.u64 t, %1; cvt.u32.u64 %0, t; }"
        : "=r"(a) : "l"(p));
    return a;
}

// ---------------- tiny utils -------------------------------------------------
__global__ void fill_i(int* p, int v, int n) {
    int i = blockIdx.x * blockDim.x + threadIdx.x;
    if (i < n) p[i] = v;
}

// ---------------- CSR build --------------------------------------------------
__global__ void hist_dst(const int* __restrict__ ei, int* __restrict__ deg) {
    int e = blockIdx.x * blockDim.x + threadIdx.x;
    if (e >= ET) return;
    int dst = (e < EE) ? ei[EE + e] : (e - EE);
    atomicAdd(&deg[dst], 1);
}

#define SCAN_ELEMS 512
__global__ void scan_s1(const int* __restrict__ deg, int* __restrict__ bsum) {
    __shared__ int sm[256];
    int base = blockIdx.x * SCAN_ELEMS;
    int t = threadIdx.x;
    int i0 = base + 2 * t, i1 = base + 2 * t + 1;
    int v = 0;
    if (i0 < NN) v += deg[i0];
    if (i1 < NN) v += deg[i1];
    sm[t] = v;
    __syncthreads();
    for (int off = 128; off > 0; off >>= 1) {
        if (t < off) sm[t] += sm[t + off];
        __syncthreads();
    }
    if (t == 0) bsum[blockIdx.x] = sm[0];
}
__global__ void scan_s2(const int* __restrict__ bsum, int* __restrict__ boff, int nb) {
    __shared__ int sm[256];
    int t = threadIdx.x;
    int v = (t < nb) ? bsum[t] : 0;
    sm[t] = v;
    __syncthreads();
    for (int off = 1; off < 256; off <<= 1) {
        int add = (t >= off) ? sm[t - off] : 0;
        __syncthreads();
        sm[t] += add;
        __syncthreads();
    }
    if (t < nb) boff[t] = sm[t] - v;   // exclusive
}
__global__ void scan_s3(const int* __restrict__ deg, const int* __restrict__ boff,
                        int* __restrict__ rowptr, int* __restrict__ cursor) {
    __shared__ int sm[256];
    int base = blockIdx.x * SCAN_ELEMS;
    int t = threadIdx.x;
    int i0 = base + 2 * t, i1 = base + 2 * t + 1;
    int v0 = (i0 < NN) ? deg[i0] : 0;
    int v1 = (i1 < NN) ? deg[i1] : 0;
    int s = v0 + v1;
    sm[t] = s;
    __syncthreads();
    for (int off = 1; off < 256; off <<= 1) {
        int add = (t >= off) ? sm[t - off] : 0;
        __syncthreads();
        sm[t] += add;
        __syncthreads();
    }
    int ex = sm[t] - s + boff[blockIdx.x];
    if (i0 < NN) { rowptr[i0] = ex;      cursor[i0] = ex; }
    if (i1 < NN) { rowptr[i1] = ex + v0; cursor[i1] = ex + v0; }
}

__global__ void csr_scatter(const int* __restrict__ ei, int* __restrict__ cursor,
                            int* __restrict__ csr) {
    int e = blockIdx.x * blockDim.x + threadIdx.x;
    if (e >= ET) return;
    int src, dst;
    if (e < EE) { src = ei[e]; dst = ei[EE + e]; }
    else        { src = dst = e - EE; }
    int pos = atomicAdd(&cursor[dst], 1);
    csr[pos] = src;
}

// ======== tf32 mma.sync GEMM + fused alpha epilogue =========================
#define TM 128
#define KCH 16
#define ASTR 20
#define BSTR 136
#define ABYTES (TM * ASTR * 4)
#define BBYTES (KCH * BSTR * 4)
#define STAGEB (ABYTES + BBYTES)
#define NSTAGE 3
#define GSMEM (NSTAGE * STAGEB)

__global__ __launch_bounds__(128, 2) void gemm_tc(const float* __restrict__ A,
                                                  const float* __restrict__ B,
                                                  __half* __restrict__ H,
                                                  const float* __restrict__ a_src,
                                                  const float* __restrict__ a_dst,
                                                  float* __restrict__ als,
                                                  float* __restrict__ ald,
                                                  int M, int K) {
    extern __shared__ float smf[];
    __shared__ float s_as[F1], s_ad[F1];
    uint32_t sbase = smem_u32(smf);
    int tid = threadIdx.x, lane = tid & 31, wid = tid >> 5;
    int wm = (wid & 1) * 64, wn = (wid >> 1) * 64;
    int row0 = blockIdx.x * TM;
    int gid = lane >> 2, tk = lane & 3;
    int niter = (K + KCH - 1) / KCH;

    s_as[tid] = a_src[tid];
    s_ad[tid] = a_dst[tid];

    float acc[4][8][4];
#pragma unroll
    for (int mi = 0; mi < 4; mi++)
#pragma unroll
        for (int ni = 0; ni < 8; ni++)
#pragma unroll
            for (int q = 0; q < 4; q++) acc[mi][ni][q] = 0.f;

    auto load_stage = [&](int s, int k0) {
        uint32_t aB = sbase + s * STAGEB;
        uint32_t bB = aB + ABYTES;
#pragma unroll
        for (int i = 0; i < 4; i++) {
            int id = tid + i * 128;
            int r = id >> 2, c4 = id & 3;
            int gk = k0 + c4 * 4;
            const float* gp = A + (size_t)(row0 + r) * K + gk;
            int remain = K - gk;
            int bytes = 16;
            if (row0 + r >= M || remain <= 0) bytes = 0;
            else if (remain < 4) bytes = remain * 4;
            uint32_t dst = aB + (uint32_t)(r * ASTR + c4 * 4) * 4u;
            asm volatile("cp.async.ca.shared.global [%0], [%1], 16, %2;"
                         :: "r"(dst), "l"(gp), "r"(bytes));
        }
#pragma unroll
        for (int i = 0; i < 4; i++) {
            int id = tid + i * 128;
            int k = id >> 5, c4 = id & 31;
            const float* gp = B + (size_t)(k0 + k) * 128 + c4 * 4;
            int bytes = (k0 + k < K) ? 16 : 0;
            uint32_t dst = bB + (uint32_t)(k * BSTR + c4 * 4) * 4u;
            asm volatile("cp.async.ca.shared.global [%0], [%1], 16, %2;"
                         :: "r"(dst), "l"(gp), "r"(bytes));
        }
        asm volatile("cp.async.commit_group;");
    };

    load_stage(0, 0);
    if (niter > 1) load_stage(1, KCH);

    for (int it = 0; it < niter; it++) {
        if (it + 1 < niter) asm volatile("cp.async.wait_group 1;");
        else                asm volatile("cp.async.wait_group 0;");
        __syncthreads();
        if (it + 2 < niter) load_stage((it + 2) % NSTAGE, (it + 2) * KCH);

        const float* As = smf + ((it % NSTAGE) * STAGEB) / 4;
        const float* Bs = As + ABYTES / 4;
#pragma unroll
        for (int ks = 0; ks < 2; ks++) {
            int kb = ks * 8;
            uint32_t af[4][4];
#pragma unroll
            for (int mi = 0; mi < 4; mi++) {
                int r = wm + mi * 16 + gid;
                af[mi][0] = __float_as_uint(As[r * ASTR + kb + tk]);
                af[mi][1] = __float_as_uint(As[(r + 8) * ASTR + kb + tk]);
                af[mi][2] = __float_as_uint(As[r * ASTR + kb + tk + 4]);
                af[mi][3] = __float_as_uint(As[(r + 8) * ASTR + kb + tk + 4]);
            }
            uint32_t bf[8][2];
#pragma unroll
            for (int ni = 0; ni < 8; ni++) {
                int c = wn + ni * 8 + gid;
                bf[ni][0] = __float_as_uint(Bs[(kb + tk) * BSTR + c]);
                bf[ni][1] = __float_as_uint(Bs[(kb + tk + 4) * BSTR + c]);
            }
#pragma unroll
            for (int mi = 0; mi < 4; mi++)
#pragma unroll
                for (int ni = 0; ni < 8; ni++) {
                    asm volatile(
                        "mma.sync.aligned.m16n8k8.row.col.f32.tf32.tf32.f32 "
                        "{%0,%1,%2,%3}, {%4,%5,%6,%7}, {%8,%9}, {%0,%1,%2,%3};"
                        : "+f"(acc[mi][ni][0]), "+f"(acc[mi][ni][1]),
                          "+f"(acc[mi][ni][2]), "+f"(acc[mi][ni][3])
                        : "r"(af[mi][0]), "r"(af[mi][1]), "r"(af[mi][2]), "r"(af[mi][3]),
                          "r"(bf[ni][0]), "r"(bf[ni][1]));
                }
        }
        __syncthreads();
    }

    // ---- fused alpha epilogue ----
#pragma unroll
    for (int mi = 0; mi < 4; mi++) {
#pragma unroll
        for (int half = 0; half < 2; half++) {
            int row = row0 + wm + mi * 16 + half * 8 + gid;
#pragma unroll
            for (int hl = 0; hl < 4; hl++) {
                float ps = 0.f, pd = 0.f;
#pragma unroll
                for (int nj = 0; nj < 2; nj++) {
                    int ni = hl * 2 + nj;
                    int c0 = wn + ni * 8 + tk * 2;
                    float q0 = acc[mi][ni][half * 2 + 0];
                    float q1 = acc[mi][ni][half * 2 + 1];
                    ps += q0 * s_as[c0] + q1 * s_as[c0 + 1];
                    pd += q0 * s_ad[c0] + q1 * s_ad[c0 + 1];
                }
                ps += __shfl_xor_sync(0xffffffffu, ps, 1);
                ps += __shfl_xor_sync(0xffffffffu, ps, 2);
                pd += __shfl_xor_sync(0xffffffffu, pd, 1);
                pd += __shfl_xor_sync(0xffffffffu, pd, 2);
                if (tk == 0 && row < M) {
                    int h = (wn >> 4) + hl;
                    als[(size_t)row * HEADS + h] = ps;
                    ald[(size_t)row * HEADS + h] = pd;
                }
            }
        }
    }

    // ---- fp16 feature store ----
#pragma unroll
    for (int mi = 0; mi < 4; mi++) {
        int r0 = row0 + wm + mi * 16 + gid;
        int r1 = r0 + 8;
#pragma unroll
        for (int ni = 0; ni < 8; ni++) {
            int c = wn + ni * 8 + tk * 2;
            if (r0 < M)
                *(__half2*)(H + (size_t)r0 * 128 + c) =
                    __floats2half2_rn(acc[mi][ni][0], acc[mi][ni][1]);
            if (r1 < M)
                *(__half2*)(H + (size_t)r1 * 128 + c) =
                    __floats2half2_rn(acc[mi][ni][2], acc[mi][ni][3]);
        }
    }
}

// ---------------- warp-per-node aggregation (layers 1,2) ---------------------
template <typename OUT>
__global__ __launch_bounds__(256) void aggregate_warp(
    const int* __restrict__ csr, const int* __restrict__ rowptr,
    const int* __restrict__ deg, const float* __restrict__ als,
    const float* __restrict__ ald, const __half* __restrict__ hfeat,
    const float* __restrict__ bias, const float* __restrict__ gamma,
    const float* __restrict__ beta, OUT* __restrict__ out) {
    int warp = (blockIdx.x * blockDim.x + threadIdx.x) >> 5;
    int l = threadIdx.x & 31;
    if (warp >= NN) return;
    int n = warp;
    int h = l >> 2;
    int c0 = l * 4;
    int start = rowptr[n];
    int len = deg[n];
    bool leader = (l & 3) == 0;
    int gsrc = l & ~3;
    float myald = leader ? __ldg(&ald[(size_t)n * HEADS + h]) : 0.f;

    float4 acc = make_float4(0.f, 0.f, 0.f, 0.f);
    float dsum = 0.f;

    auto edge = [&](int s) {
        const __half2* hp = (const __half2*)(hfeat + (size_t)s * F1) + l * 2;
        __half2 q0 = __ldg(hp);
        __half2 q1 = __ldg(hp + 1);
        float p = 0.f;
        if (leader) {
            float al = __ldg(&als[(size_t)s * HEADS + h]) + myald;
            al = al > 0.f ? al : 0.2f * al;
            p = __expf(al);
        }
        p = __shfl_sync(0xffffffffu, p, gsrc);
        dsum += p;
        float2 f0 = __half22float2(q0);
        float2 f1 = __half22float2(q1);
        acc.x = fmaf(p, f0.x, acc.x);
        acc.y = fmaf(p, f0.y, acc.y);
        acc.z = fmaf(p, f1.x, acc.z);
        acc.w = fmaf(p, f1.y, acc.w);
    };

    int i = 0;
    for (; i + 4 <= len; i += 4) {
        int s0 = __ldg(&csr[start + i]);
        int s1 = __ldg(&csr[start + i + 1]);
        int s2 = __ldg(&csr[start + i + 2]);
        int s3 = __ldg(&csr[start + i + 3]);
        edge(s0); edge(s1); edge(s2); edge(s3);
    }
    for (; i < len; i++) {
        int s0 = __ldg(&csr[start + i]);
        edge(s0);
    }

    float invd = 1.f / fmaxf(dsum, 1e-16f);
    float4 bb = *(const float4*)(bias + c0);
    float4 gg = *(const float4*)(gamma + c0);
    float4 be = *(const float4*)(beta + c0);
    float bnf = rsqrtf(1.0f + 1e-5f);
    float v0 = acc.x * invd + bb.x;
    float v1 = acc.y * invd + bb.y;
    float v2 = acc.z * invd + bb.z;
    float v3 = acc.w * invd + bb.w;
    v0 = v0 > 0.f ? v0 : (__expf(v0) - 1.f);
    v1 = v1 > 0.f ? v1 : (__expf(v1) - 1.f);
    v2 = v2 > 0.f ? v2 : (__expf(v2) - 1.f);
    v3 = v3 > 0.f ? v3 : (__expf(v3) - 1.f);
    float r0 = v0 * gg.x * bnf + be.x;
    float r1 = v1 * gg.y * bnf + be.y;
    float r2 = v2 * gg.z * bnf + be.z;
    float r3 = v3 * gg.w * bnf + be.w;
    if constexpr (sizeof(OUT) == 2) {
        __half2* op = (__half2*)((__half*)out + (size_t)n * F1 + c0);
        op[0] = __floats2half2_rn(r0, r1);
        op[1] = __floats2half2_rn(r2, r3);
    } else {
        *(float4*)((float*)out + (size_t)n * F1 + c0) = make_float4(r0, r1, r2, r3);
    }
}

// ---------------- layer 3: fused GEMM(128->10) + node alphas (fp16 in/out) ---
__global__ void gemm10_alpha(const __half* __restrict__ A, const float* __restrict__ W,
                             const float* __restrict__ a3s, const float* __restrict__ a3d,
                             __half* __restrict__ C, float* __restrict__ als,
                             float* __restrict__ ald) {
    __shared__ float Ws[F1 * NCLS];
    for (int i = threadIdx.x; i < F1 * NCLS; i += blockDim.x) Ws[i] = W[i];
    __syncthreads();
    int warp = (blockIdx.x * blockDim.x + threadIdx.x) >> 5;
    int lane = threadIdx.x & 31;
    if (warp >= NN) return;
    float acc[NCLS];
#pragma unroll
    for (int c = 0; c < NCLS; c++) acc[c] = 0.f;
    const __half2* arow = (const __half2*)(A + (size_t)warp * F1);
#pragma unroll
    for (int q = 0; q < 2; q++) {
        int k2 = lane + q * 32;
        float2 av = __half22float2(__ldg(arow + k2));
        int k = k2 * 2;
#pragma unroll
        for (int c = 0; c < NCLS; c++)
            acc[c] += av.x * Ws[k * NCLS + c] + av.y * Ws[(k + 1) * NCLS + c];
    }
#pragma unroll
    for (int off = 16; off > 0; off >>= 1)
#pragma unroll
        for (int c = 0; c < NCLS; c++) acc[c] += __shfl_xor_sync(0xffffffffu, acc[c], off);
    if (lane < NCLS) C[(size_t)warp * NCLS + lane] = __float2half_rn(acc[lane]);
    if (lane == 0) {
        float s = 0.f, d = 0.f;
#pragma unroll
        for (int c = 0; c < NCLS; c++) {
            s += acc[c] * __ldg(&a3s[c]);
            d += acc[c] * __ldg(&a3d[c]);
        }
        als[warp] = s;
        ald[warp] = d;
    }
}

// ---------------- layer 3: half-warp-per-edge aggregation + log_softmax ------
__global__ __launch_bounds__(128) void aggregate10_lsm(
    const int* __restrict__ csr, const int* __restrict__ rowptr,
    const int* __restrict__ deg, const float* __restrict__ als,
    const float* __restrict__ ald, const __half* __restrict__ hfeat,
    const float* __restrict__ b3, float* __restrict__ out) {
    int warp = (blockIdx.x * blockDim.x + threadIdx.x) >> 5;
    int lane = threadIdx.x & 31;
    if (warp >= NN) return;
    int n = warp;
    int start = rowptr[n];
    int len = deg[n];
    int hl = lane & 15;              // lane within half-warp
    int half = lane >> 4;            // 0: even edges, 1: odd edges
    bool hleader = (hl == 0);
    int bsrc = half << 4;            // broadcast source lane (0 or 16)
    // per-half shfl mask: the two halves have independent trip counts
    unsigned hmask = half ? 0xffff0000u : 0x0000ffffu;
    float myald = hleader ? __ldg(&ald[n]) : 0.f;
    float acc = 0.f, dsum = 0.f;

    auto edge = [&](int s) {
        float f = (hl < NCLS) ? __half2float(__ldg(&hfeat[(size_t)s * NCLS + hl])) : 0.f;
        float p = 0.f;
        if (hleader) {
            float l0 = __ldg(&als[s]) + myald;
            l0 = l0 > 0.f ? l0 : 0.2f * l0;
            p = __expf(l0);
        }
        p = __shfl_sync(hmask, p, bsrc);
        dsum += p;
        acc = fmaf(p, f, acc);
    };

    int i = half;
    for (; i + 2 < len; i += 4) {          // each half handles 2 edges per iter
        int s0 = __ldg(&csr[start + i]);
        int s1 = __ldg(&csr[start + i + 2]);
        edge(s0);
        edge(s1);
    }
    if (i < len) {
        int s0 = __ldg(&csr[start + i]);
        edge(s0);
    }

    // merge the two half-warps (structurally convergent: every lane reaches here)
    acc  += __shfl_xor_sync(0xffffffffu, acc, 16);
    dsum += __shfl_xor_sync(0xffffffffu, dsum, 16);

    float invd = 1.f / fmaxf(dsum, 1e-16f);
    float val = (hl < NCLS) ? acc * invd + __ldg(&b3[hl]) : -1e30f;
    float m = val;
#pragma unroll
    for (int off = 8; off > 0; off >>= 1)
        m = fmaxf(m, __shfl_xor_sync(0xffffffffu, m, off));
    float ex = (hl < NCLS) ? expf(val - m) : 0.f;
    float ssum = ex;
#pragma unroll
    for (int off = 8; off > 0; off >>= 1)
        ssum += __shfl_xor_sync(0xffffffffu, ssum, off);
    float l = m + logf(ssum);
    if (half == 0 && hl < NCLS) out[(size_t)n * NCLS + hl] = val - l;
}

// ---------------- driver -----------------------------------------------------
extern "C" void kernel_launch(void* const* d_in, const int* in_sizes, int n_in,
                              void* d_out, int out_size) {
    const float* x    = (const float*)d_in[0];
    const int*   ei   = (const int*)d_in[1];
    const float* W1   = (const float*)d_in[2];
    const float* a1s  = (const float*)d_in[3];
    const float* a1d  = (const float*)d_in[4];
    const float* b1   = (const float*)d_in[5];
    const float* g1   = (const float*)d_in[6];
    const float* be1  = (const float*)d_in[7];
    const float* W2   = (const float*)d_in[8];
    const float* a2s  = (const float*)d_in[9];
    const float* a2d  = (const float*)d_in[10];
    const float* b2   = (const float*)d_in[11];
    const float* g2   = (const float*)d_in[12];
    const float* be2  = (const float*)d_in[13];
    const float* W3   = (const float*)d_in[14];
    const float* a3s  = (const float*)d_in[15];
    const float* a3d  = (const float*)d_in[16];
    const float* b3   = (const float*)d_in[17];
    float* out = (float*)d_out;

    __half *bufH, *bufH2;
    float *bufB, *als, *ald;
    int *deg, *rowptr, *cursor, *bsum, *boff, *csr;
    cudaGetSymbolAddress((void**)&bufH, g_bufH);
    cudaGetSymbolAddress((void**)&bufH2, g_bufH2);
    cudaGetSymbolAddress((void**)&bufB, g_bufB);
    cudaGetSymbolAddress((void**)&als, g_als);
    cudaGetSymbolAddress((void**)&ald, g_ald);
    cudaGetSymbolAddress((void**)&deg, g_deg);
    cudaGetSymbolAddress((void**)&rowptr, g_rowptr);
    cudaGetSymbolAddress((void**)&cursor, g_cursor);
    cudaGetSymbolAddress((void**)&bsum, g_bsum);
    cudaGetSymbolAddress((void**)&boff, g_boff);
    cudaGetSymbolAddress((void**)&csr, g_csr);

    cudaFuncSetAttribute(gemm_tc, cudaFuncAttributeMaxDynamicSharedMemorySize, GSMEM);

    static cudaStream_t s2 = nullptr;
    static cudaEvent_t evFork = nullptr, evJoin = nullptr;
    if (s2 == nullptr) {
        cudaStreamCreate(&s2);
        cudaEventCreateWithFlags(&evFork, cudaEventDisableTiming);
        cudaEventCreateWithFlags(&evJoin, cudaEventDisableTiming);
    }

    const int TB = 256;
    const int NB_SCAN = cdiv(NN, SCAN_ELEMS);
    const int NGRID = cdiv(NN, TM);
    const int AGRID = cdiv(NN * 32, TB);

    // ---- fork: CSR build on s2, GEMM1 on main stream ----
    cudaEventRecord(evFork, 0);
    cudaStreamWaitEvent(s2, evFork, 0);

    fill_i<<<cdiv(NN, TB), TB, 0, s2>>>(deg, 0, NN);
    hist_dst<<<cdiv(ET, TB), TB, 0, s2>>>(ei, deg);
    scan_s1<<<NB_SCAN, 256, 0, s2>>>(deg, bsum);
    scan_s2<<<1, 256, 0, s2>>>(bsum, boff, NB_SCAN);
    scan_s3<<<NB_SCAN, 256, 0, s2>>>(deg, boff, rowptr, cursor);
    csr_scatter<<<cdiv(ET, TB), TB, 0, s2>>>(ei, cursor, csr);
    cudaEventRecord(evJoin, s2);

    gemm_tc<<<NGRID, 128, GSMEM>>>(x, W1, bufH, a1s, a1d, als, ald, NN, F_IN);

    cudaStreamWaitEvent(0, evJoin, 0);

    // ---- layer 1 aggregation (fp32 out -> GEMM2 input) ----
    aggregate_warp<float><<<AGRID, TB>>>(csr, rowptr, deg, als, ald, bufH,
                                         b1, g1, be1, bufB);

    // ---- layer 2 ----
    gemm_tc<<<NGRID, 128, GSMEM>>>(bufB, W2, bufH, a2s, a2d, als, ald, NN, F1);
    aggregate_warp<__half><<<AGRID, TB>>>(csr, rowptr, deg, als, ald, bufH,
                                          b2, g2, be2, bufH2);

    // ---- layer 3 (bufH free after agg2; reuse as fp16 logits buffer) ----
    gemm10_alpha<<<AGRID, TB>>>(bufH2, W3, a3s, a3d, bufH, als, ald);
    aggregate10_lsm<<<cdiv(NN * 32, 128), 128>>>(csr, rowptr, deg, als, ald, bufH, b3, out);
}